// round 13
// baseline (speedup 1.0000x reference)
#include <cuda_runtime.h>
#include <cstdint>

#define DEVINL __device__ __forceinline__

constexpr int Bc = 4, Sc = 2048, Dc = 1024, Hc = 16;
constexpr int Mc = Bc * Sc;           // 8192
constexpr int NQKV = 3 * Dc;          // 3072

// ---------------------------------------------------------------------------
// Scratch (__device__ globals). All fp16 data stored as packed f16x2 words.
// ---------------------------------------------------------------------------
__device__ uint32_t g_xh[(size_t)Mc * 512];                              // x hi [8192][512]
__device__ uint32_t g_wth[(size_t)NQKV * 512];                           // wA^T hi [3072][512]
__device__ uint32_t g_wph[(size_t)Dc * 512];                             // wP^T hi [1024][512]
__device__ uint32_t g_qh[(size_t)64 * Sc * 32];                          // q hi [64][2048][32]
__device__ uint32_t g_kh[(size_t)64 * Sc * 32];                          // k hi
__device__ uint32_t g_vh[(size_t)64 * Sc * 32];                          // v hi
__device__ uint32_t g_ah[(size_t)Mc * 512];                              // attn hi [8192][512]

// ---------------------------------------------------------------------------
// Helpers
// ---------------------------------------------------------------------------
DEVINL uint32_t pack_h2(float x0, float x1) {
    uint32_t h;
    asm("cvt.rn.f16x2.f32 %0, %1, %2;" : "=r"(h) : "f"(x1), "f"(x0));
    return h;
}
DEVINL uint32_t ex2_h2(float d0, float d1) {
    uint32_t din = pack_h2(d0, d1);
    uint32_t r;
    asm("ex2.approx.f16x2 %0, %1;" : "=r"(r) : "r"(din));
    return r;
}
DEVINL void mma_f16(float d[4], const uint32_t a[4], const uint32_t b[2], const float c[4]) {
    asm volatile(
        "mma.sync.aligned.m16n8k16.row.col.f32.f16.f16.f32 "
        "{%0,%1,%2,%3}, {%4,%5,%6,%7}, {%8,%9}, {%10,%11,%12,%13};\n"
        : "=f"(d[0]), "=f"(d[1]), "=f"(d[2]), "=f"(d[3])
        : "r"(a[0]), "r"(a[1]), "r"(a[2]), "r"(a[3]),
          "r"(b[0]), "r"(b[1]),
          "f"(c[0]), "f"(c[1]), "f"(c[2]), "f"(c[3]));
}
DEVINL void ldsm_x4(uint32_t addr, uint32_t& r0, uint32_t& r1, uint32_t& r2, uint32_t& r3) {
    asm volatile("ldmatrix.sync.aligned.m8n8.x4.shared.b16 {%0,%1,%2,%3}, [%4];"
                 : "=r"(r0), "=r"(r1), "=r"(r2), "=r"(r3) : "r"(addr));
}
DEVINL void ldsm_x4_t(uint32_t addr, uint32_t& r0, uint32_t& r1, uint32_t& r2, uint32_t& r3) {
    asm volatile("ldmatrix.sync.aligned.m8n8.x4.trans.shared.b16 {%0,%1,%2,%3}, [%4];"
                 : "=r"(r0), "=r"(r1), "=r"(r2), "=r"(r3) : "r"(addr));
}
DEVINL void cp16(void* s, const void* g) {
    uint32_t sa = (uint32_t)__cvta_generic_to_shared(s);
    asm volatile("cp.async.cg.shared.global [%0], [%1], 16;\n" :: "r"(sa), "l"(g));
}
DEVINL void cp_commit() { asm volatile("cp.async.commit_group;\n"); }
template <int N> DEVINL void cp_wait() { asm volatile("cp.async.wait_group %0;\n" :: "n"(N)); }

// ---------------------------------------------------------------------------
// Pre-pass 1: round x (fp32 [8192][1024]) -> g_xh (f16x2 words)
// ---------------------------------------------------------------------------
__global__ void conv_x(const float* __restrict__ x)
{
    size_t idx = (size_t)blockIdx.x * 1024 + threadIdx.x;   // 4M words
    float2 v = ((const float2*)x)[idx];
    g_xh[idx] = pack_h2(v.x, v.y);
}

// ---------------------------------------------------------------------------
// Pre-pass 2: transpose + round W (fp32 [1024][N]) -> [N][512 words] hi only.
// ---------------------------------------------------------------------------
__global__ void conv_wT(const float* __restrict__ W, int N, int which)
{
    __shared__ float ts[64][33];
    uint32_t* Wh = which ? g_wph : g_wth;
    const int k0 = blockIdx.x * 64, n0 = blockIdx.y * 32;
    const int tx = threadIdx.x, ty = threadIdx.y;
#pragma unroll
    for (int i = 0; i < 8; i++)
        ts[ty + i * 8][tx] = W[(size_t)(k0 + ty + i * 8) * N + n0 + tx];
    __syncthreads();
#pragma unroll
    for (int i = 0; i < 4; i++) {
        int n = ty + i * 8;
        Wh[(size_t)(n0 + n) * 512 + (k0 >> 1) + tx] = pack_h2(ts[2 * tx][n], ts[2 * tx + 1][n]);
    }
}

// ---------------------------------------------------------------------------
// fp16 1-term GEMM: C = A(Mx1024) W^T + bias.
// CTA 128x128, BK=64 (16 iters, 64 mma/iter), 3-stage cp.async, 2 CTAs/SM.
// EPI=0: A=x -> scatter q/k/v hi (head-major). EPI=1: A=attn -> out fp32.
// ---------------------------------------------------------------------------
constexpr int P_LD = 36;                       // words/row (32 + 4 pad)
constexpr int P_ARR_W = 128 * P_LD;            // 4608 words
constexpr int P_ARR_B = P_ARR_W * 4;           // 18432 B
constexpr int P_STG_W = 2 * P_ARR_W;           // 9216 words (A | B)
constexpr int P_STG_B = P_STG_W * 4;           // 36864 B
constexpr int G_SMEM = 3 * P_STG_B;            // 110592 B

template <int EPI>
__global__ void __launch_bounds__(256, 2)
h_gemm(const float* __restrict__ bias, float* __restrict__ out)
{
    extern __shared__ uint32_t sw[];
    const uint32_t* Agh = EPI ? g_ah : g_xh;
    const uint32_t* Bgh = EPI ? g_wph : g_wth;

    const int tid = threadIdx.x, wid = tid >> 5, lid = tid & 31;
    const int wm = wid >> 2, wn = wid & 3;
    const int g = lid >> 2, tg = lid & 3;
    const int cm = blockIdx.y * 128, cn = blockIdx.x * 128;
    const uint32_t smb = (uint32_t)__cvta_generic_to_shared(sw);

    const uint32_t a_fb = smb + 4u * ((wm * 64 + (lid & 15)) * P_LD + (lid >> 4) * 4);
    const uint32_t b_fb = smb + 4u * ((wn * 32 + ((lid >> 4) & 1) * 8 + (lid & 7)) * P_LD
                                      + ((lid >> 3) & 1) * 4) + (uint32_t)P_ARR_B;

    const int row = tid >> 1;                  // 0..127
    const int ch0 = (tid & 1) * 4;             // 4 16B-chunks per thread per array

    auto load_stage = [&](int kt, int s) {
#pragma unroll
        for (int i = 0; i < 4; i++) {
            int c = ch0 + i;
            uint32_t dst = (uint32_t)(s * P_STG_W + row * P_LD + c * 4);
            size_t asrc = (size_t)(cm + row) * 512 + kt * 32 + c * 4;
            size_t bsrc = (size_t)(cn + row) * 512 + kt * 32 + c * 4;
            cp16(sw + dst,           Agh + asrc);
            cp16(sw + dst + P_ARR_W, Bgh + bsrc);
        }
    };

    float acc[4][4][4];
#pragma unroll
    for (int i = 0; i < 4; i++)
#pragma unroll
        for (int j = 0; j < 4; j++)
#pragma unroll
            for (int e = 0; e < 4; e++) acc[i][j][e] = 0.f;

    constexpr int NT = 16;                     // K=1024 / 64
    load_stage(0, 0); cp_commit();
    load_stage(1, 1); cp_commit();

    for (int kt = 0; kt < NT; kt++) {
        cp_wait<1>();
        __syncthreads();
        if (kt + 2 < NT) load_stage(kt + 2, (kt + 2) % 3);
        cp_commit();

        const uint32_t sb = (uint32_t)((kt % 3) * P_STG_B);
#pragma unroll
        for (int ks = 0; ks < 4; ks++) {
            uint32_t ah[4][4], b[4][2];
#pragma unroll
            for (int mi = 0; mi < 4; mi++) {
                uint32_t ad = a_fb + sb + 4u * (mi * 16 * P_LD + ks * 8);
                ldsm_x4(ad, ah[mi][0], ah[mi][1], ah[mi][2], ah[mi][3]);
            }
#pragma unroll
            for (int p = 0; p < 2; p++)
                ldsm_x4(b_fb + sb + 4u * (p * 16 * P_LD + ks * 8),
                        b[2 * p][0], b[2 * p][1], b[2 * p + 1][0], b[2 * p + 1][1]);
#pragma unroll
            for (int mi = 0; mi < 4; mi++)
#pragma unroll
                for (int nj = 0; nj < 4; nj++)
                    mma_f16(acc[mi][nj], ah[mi], b[nj], acc[mi][nj]);
        }
    }

    // Epilogue
#pragma unroll
    for (int mi = 0; mi < 4; mi++) {
#pragma unroll
        for (int nj = 0; nj < 4; nj++) {
            int col0 = cn + wn * 32 + nj * 8 + 2 * tg;       // even
            float2 v0 = make_float2(acc[mi][nj][0] + bias[col0],
                                    acc[mi][nj][1] + bias[col0 + 1]);
            float2 v1 = make_float2(acc[mi][nj][2] + bias[col0],
                                    acc[mi][nj][3] + bias[col0 + 1]);
            int row0 = cm + wm * 64 + mi * 16 + g;
            int row1 = row0 + 8;
            if (EPI == 1) {
                *(float2*)&out[(size_t)row0 * 1024 + col0] = v0;
                *(float2*)&out[(size_t)row1 * 1024 + col0] = v1;
            } else {
                int t = col0 >> 10;                // 0:q 1:k 2:v
                int r1 = col0 & 1023;
                int h = r1 >> 6, d = r1 & 63;      // d even
                int b0 = row0 >> 11, s0 = row0 & 2047;
                int b1 = row1 >> 11, s1 = row1 & 2047;
                size_t w0 = ((size_t)(b0 * Hc + h) * Sc + s0) * 32 + (d >> 1);
                size_t w1 = ((size_t)(b1 * Hc + h) * Sc + s1) * 32 + (d >> 1);
                uint32_t* dst = (t == 0) ? g_qh : (t == 1) ? g_kh : g_vh;
                dst[w0] = pack_h2(v0.x, v0.y);
                dst[w1] = pack_h2(v1.x, v1.y);
            }
        }
    }
}

// ---------------------------------------------------------------------------
// Flash attention: causal, hd=64, k-blocks of 64, fp16 1-term QK^T.
// Softmax: ex2.approx.f16x2 -> packed P fragments. Row-sum l accumulated by
// a ones-vector mma. 3-stage cp.async. 2 CTAs/SM. Heavy q-blocks first.
// ---------------------------------------------------------------------------
constexpr int F_LD = 36;                       // words per 64-half row
constexpr int F_TW = 64 * F_LD;                // 2304 words per stage
constexpr int F_VB0 = 3 * F_TW;                // V area word offset
constexpr int FLASH_SMEM = 6 * F_TW * 4;       // 55296 B

__global__ void __launch_bounds__(256, 2)
flash_kernel()
{
    extern __shared__ uint32_t smw[];
    const uint32_t smb = (uint32_t)__cvta_generic_to_shared(smw);

    const int tid = threadIdx.x, wid = tid >> 5, lid = tid & 31;
    const int g = lid >> 2, tg = lid & 3;
    const int qb = (int)gridDim.x - 1 - (int)blockIdx.x;   // heavy blocks first
    const int head = blockIdx.y;

    const uint32_t* Qh = g_qh + (size_t)head * Sc * 32 + (size_t)qb * 128 * 32;
    const uint32_t* Kh = g_kh + (size_t)head * Sc * 32;
    const uint32_t* Vh = g_vh + (size_t)head * Sc * 32;

    // Stage Q hi -> V area (128 rows x 36w stride).
#pragma unroll
    for (int i = 0; i < 4; i++) {
        int idx = tid + i * 256;
        int r = idx >> 3, c = idx & 7;
        cp16(smw + F_VB0 + r * F_LD + c * 4, Qh + (size_t)r * 32 + c * 4);
    }
    cp_commit();
    cp_wait<0>();
    __syncthreads();

    uint32_t qh[4][4];
    {
        uint32_t qo = smb + 4u * F_VB0
                    + 4u * ((wid * 16 + (lid & 15)) * F_LD + (lid >> 4) * 4);
#pragma unroll
        for (int ks = 0; ks < 4; ks++)
            ldsm_x4(qo + 4u * (ks * 8), qh[ks][0], qh[ks][1], qh[ks][2], qh[ks][3]);
    }
    __syncthreads();                           // K/V areas now reusable

    auto load_tile = [&](int kb, int s) {
        size_t kbase = (size_t)kb * 64;
#pragma unroll
        for (int i = 0; i < 2; i++) {
            int idx = tid + i * 256;
            int r = idx >> 3, c = idx & 7;
            uint32_t dk = (uint32_t)(s * F_TW + r * F_LD + c * 4);
            cp16(smw + dk,         Kh + (kbase + r) * 32 + c * 4);
            cp16(smw + F_VB0 + dk, Vh + (kbase + r) * 32 + c * 4);
        }
    };

    const int nkb = 2 * qb + 2;                // 64-wide k-blocks
    load_tile(0, 0); cp_commit();
    load_tile(1, 1); cp_commit();

    float o[8][4];
#pragma unroll
    for (int j = 0; j < 8; j++)
#pragma unroll
        for (int e = 0; e < 4; e++) o[j][e] = 0.f;
    float lacc[4] = {0.f, 0.f, 0.f, 0.f};      // row-sum accumulator (ones-mma)
    float m0 = -1e30f, m1 = -1e30f;

    const float scale = 0.125f;
    const float LOG2E = 1.4426950408889634f;
    const int row0g = qb * 128 + wid * 16 + g;
    const int row1g = row0g + 8;
    const uint32_t b_ones[2] = {0x3C003C00u, 0x3C003C00u};   // f16 1.0 x2

    const uint32_t k_fb = smb + 4u * ((((lid >> 4) & 1) * 8 + (lid & 7)) * F_LD
                                      + ((lid >> 3) & 1) * 4);
    const uint32_t v_fb = smb + 4u * F_VB0
                        + 4u * ((((lid >> 3) & 1) * 8 + (lid & 7)) * F_LD)
                        + (uint32_t)(lid >> 4) * 16;

    for (int kb = 0; kb < nkb; kb++) {
        cp_wait<1>();
        __syncthreads();
        if (kb + 2 < nkb) load_tile(kb + 2, (kb + 2) % 3);
        cp_commit();

        const uint32_t stb = (uint32_t)((kb % 3) * F_TW * 4);

        // S = Q K^T (16 q-rows x 64 k-cols per warp), fp16 1-term
        float sacc[8][4];
#pragma unroll
        for (int nj = 0; nj < 8; nj++)
#pragma unroll
            for (int e = 0; e < 4; e++) sacc[nj][e] = 0.f;
#pragma unroll
        for (int ks = 0; ks < 4; ks++) {
            uint32_t kd = k_fb + stb + 4u * (ks * 8);
#pragma unroll
            for (int p = 0; p < 2; p++) {
                uint32_t b0[2], b1[2];
                ldsm_x4(kd + 4u * (2 * p * 16 * F_LD), b0[0], b0[1], b1[0], b1[1]);
                mma_f16(sacc[4 * p],     qh[ks], b0, sacc[4 * p]);
                mma_f16(sacc[4 * p + 1], qh[ks], b1, sacc[4 * p + 1]);
                uint32_t c0[2], c1[2];
                ldsm_x4(kd + 4u * ((2 * p + 1) * 16 * F_LD), c0[0], c0[1], c1[0], c1[1]);
                mma_f16(sacc[4 * p + 2], qh[ks], c0, sacc[4 * p + 2]);
                mma_f16(sacc[4 * p + 3], qh[ks], c1, sacc[4 * p + 3]);
            }
        }

        // scale + causal mask
#pragma unroll
        for (int nj = 0; nj < 8; nj++) {
#pragma unroll
            for (int e = 0; e < 4; e++) {
                int col = kb * 64 + nj * 8 + 2 * tg + (e & 1);
                int row = (e & 2) ? row1g : row0g;
                float v = sacc[nj][e] * scale;
                sacc[nj][e] = (col > row) ? -1e30f : v;
            }
        }

        // online softmax: row max
        float rmax0 = -1e30f, rmax1 = -1e30f;
#pragma unroll
        for (int nj = 0; nj < 8; nj++) {
            rmax0 = fmaxf(rmax0, fmaxf(sacc[nj][0], sacc[nj][1]));
            rmax1 = fmaxf(rmax1, fmaxf(sacc[nj][2], sacc[nj][3]));
        }
        rmax0 = fmaxf(rmax0, __shfl_xor_sync(0xffffffffu, rmax0, 1));
        rmax0 = fmaxf(rmax0, __shfl_xor_sync(0xffffffffu, rmax0, 2));
        rmax1 = fmaxf(rmax1, __shfl_xor_sync(0xffffffffu, rmax1, 1));
        rmax1 = fmaxf(rmax1, __shfl_xor_sync(0xffffffffu, rmax1, 2));

        float nm0 = fmaxf(m0, rmax0), nm1 = fmaxf(m1, rmax1);
        float alpha0 = exp2f((m0 - nm0) * LOG2E);
        float alpha1 = exp2f((m1 - nm1) * LOG2E);
        float c0 = nm0 * LOG2E, c1 = nm1 * LOG2E;

        // exponentials in fp16x2: result IS the packed P fragment word
        uint32_t pp[8], pq[8];
#pragma unroll
        for (int nj = 0; nj < 8; nj++) {
            pp[nj] = ex2_h2(fmaf(sacc[nj][0], LOG2E, -c0), fmaf(sacc[nj][1], LOG2E, -c0));
            pq[nj] = ex2_h2(fmaf(sacc[nj][2], LOG2E, -c1), fmaf(sacc[nj][3], LOG2E, -c1));
        }

        m0 = nm0; m1 = nm1;
        lacc[0] *= alpha0; lacc[1] *= alpha0;
        lacc[2] *= alpha1; lacc[3] *= alpha1;
#pragma unroll
        for (int j = 0; j < 8; j++) {
            o[j][0] *= alpha0; o[j][1] *= alpha0;
            o[j][2] *= alpha1; o[j][3] *= alpha1;
        }

        // O += P V, and lacc += P * ones (row sums via tensor core)
#pragma unroll
        for (int ks = 0; ks < 4; ks++) {
            uint32_t pa[4];
            pa[0] = pp[2 * ks];
            pa[1] = pq[2 * ks];
            pa[2] = pp[2 * ks + 1];
            pa[3] = pq[2 * ks + 1];
            mma_f16(lacc, pa, b_ones, lacc);
            uint32_t vd = v_fb + stb + 4u * (ks * 16 * F_LD);
#pragma unroll
            for (int p = 0; p < 4; p++) {
                uint32_t b0[2], b1[2];
                ldsm_x4_t(vd + (uint32_t)p * 32, b0[0], b0[1], b1[0], b1[1]);
                mma_f16(o[2 * p],     pa, b0, o[2 * p]);
                mma_f16(o[2 * p + 1], pa, b1, o[2 * p + 1]);
            }
        }
    }

    // Epilogue: write attn as fp16 hi into g_ah [8192][512 words]
    {
        int b = head >> 4, h = head & 15;
        int s0 = qb * 128 + wid * 16 + g;
        float inv0 = 1.f / lacc[0], inv1 = 1.f / lacc[2];
        size_t base0 = ((size_t)b * Sc + s0) * 512 + h * 32;
        size_t base1 = ((size_t)b * Sc + s0 + 8) * 512 + h * 32;
#pragma unroll
        for (int nj = 0; nj < 8; nj++) {
            int dw = nj * 4 + tg;
            g_ah[base0 + dw] = pack_h2(o[nj][0] * inv0, o[nj][1] * inv0);
            g_ah[base1 + dw] = pack_h2(o[nj][2] * inv1, o[nj][3] * inv1);
        }
    }
}

// ---------------------------------------------------------------------------
extern "C" void kernel_launch(void* const* d_in, const int* in_sizes, int n_in,
                              void* d_out, int out_size)
{
    (void)in_sizes; (void)n_in; (void)out_size;
    const float* x      = (const float*)d_in[0];
    const float* w_attn = (const float*)d_in[2];
    const float* b_attn = (const float*)d_in[3];
    const float* w_proj = (const float*)d_in[4];
    const float* b_proj = (const float*)d_in[5];
    float* out = (float*)d_out;

    cudaFuncSetAttribute(h_gemm<0>,    cudaFuncAttributeMaxDynamicSharedMemorySize, G_SMEM);
    cudaFuncSetAttribute(h_gemm<1>,    cudaFuncAttributeMaxDynamicSharedMemorySize, G_SMEM);
    cudaFuncSetAttribute(flash_kernel, cudaFuncAttributeMaxDynamicSharedMemorySize, FLASH_SMEM);

    // Pre-pass: round/transpose inputs to fp16
    conv_x<<<(Mc * 512) / 1024, 1024>>>(x);
    conv_wT<<<dim3(16, NQKV / 32), dim3(32, 8)>>>(w_attn, NQKV, 0);
    conv_wT<<<dim3(16, Dc / 32),   dim3(32, 8)>>>(w_proj, Dc, 1);

    // 1) QKV GEMM (1-term, BK=64) -> q/k/v hi (head-major)
    h_gemm<0><<<dim3(NQKV / 128, Mc / 128), 256, G_SMEM>>>(b_attn, nullptr);
    // 2) causal flash attention -> attn hi
    flash_kernel<<<dim3(Sc / 128, Bc * Hc), 256, FLASH_SMEM>>>();
    // 3) proj GEMM (1-term, BK=64) -> out fp32
    h_gemm<1><<<dim3(Dc / 128, Mc / 128), 256, G_SMEM>>>(b_proj, out);
}

// round 14
// speedup vs baseline: 1.1091x; 1.1091x over previous
#include <cuda_runtime.h>
#include <cstdint>

#define DEVINL __device__ __forceinline__

constexpr int Bc = 4, Sc = 2048, Dc = 1024, Hc = 16;
constexpr int Mc = Bc * Sc;           // 8192
constexpr int NQKV = 3 * Dc;          // 3072

// ---------------------------------------------------------------------------
// Scratch (__device__ globals). All fp16 data stored as packed f16x2 words.
// ---------------------------------------------------------------------------
__device__ uint32_t g_xh[(size_t)Mc * 512];                              // x hi [8192][512]
__device__ uint32_t g_wth[(size_t)NQKV * 512];                           // wA^T hi [3072][512]
__device__ uint32_t g_wph[(size_t)Dc * 512];                             // wP^T hi [1024][512]
__device__ uint32_t g_qh[(size_t)64 * Sc * 32];                          // q hi [64][2048][32]
__device__ uint32_t g_kh[(size_t)64 * Sc * 32];                          // k hi
__device__ uint32_t g_vh[(size_t)64 * Sc * 32];                          // v hi
__device__ uint32_t g_ah[(size_t)Mc * 512];                              // attn hi [8192][512]

// ---------------------------------------------------------------------------
// Helpers
// ---------------------------------------------------------------------------
DEVINL uint32_t pack_h2(float x0, float x1) {
    uint32_t h;
    asm("cvt.rn.f16x2.f32 %0, %1, %2;" : "=r"(h) : "f"(x1), "f"(x0));
    return h;
}
DEVINL void unpack_h2(uint32_t h, float& x0, float& x1) {
    asm("{\n\t.reg .f16 lo, hi;\n\tmov.b32 {lo, hi}, %2;\n\t"
        "cvt.f32.f16 %0, lo;\n\tcvt.f32.f16 %1, hi;\n\t}"
        : "=f"(x0), "=f"(x1) : "r"(h));
}
DEVINL uint32_t ex2_h2(float d0, float d1) {
    uint32_t din = pack_h2(d0, d1);
    uint32_t r;
    asm("ex2.approx.f16x2 %0, %1;" : "=r"(r) : "r"(din));
    return r;
}
DEVINL void mma_f16(float d[4], const uint32_t a[4], const uint32_t b[2], const float c[4]) {
    asm volatile(
        "mma.sync.aligned.m16n8k16.row.col.f32.f16.f16.f32 "
        "{%0,%1,%2,%3}, {%4,%5,%6,%7}, {%8,%9}, {%10,%11,%12,%13};\n"
        : "=f"(d[0]), "=f"(d[1]), "=f"(d[2]), "=f"(d[3])
        : "r"(a[0]), "r"(a[1]), "r"(a[2]), "r"(a[3]),
          "r"(b[0]), "r"(b[1]),
          "f"(c[0]), "f"(c[1]), "f"(c[2]), "f"(c[3]));
}
// fp16-accumulator mma (2x HMMA rate); D/C are f16x2 pairs.
DEVINL void mma_f16acc(uint32_t d[2], const uint32_t a[4], const uint32_t b[2], const uint32_t c[2]) {
    asm volatile(
        "mma.sync.aligned.m16n8k16.row.col.f16.f16.f16.f16 "
        "{%0,%1}, {%2,%3,%4,%5}, {%6,%7}, {%8,%9};\n"
        : "=r"(d[0]), "=r"(d[1])
        : "r"(a[0]), "r"(a[1]), "r"(a[2]), "r"(a[3]),
          "r"(b[0]), "r"(b[1]),
          "r"(c[0]), "r"(c[1]));
}
DEVINL void ldsm_x4(uint32_t addr, uint32_t& r0, uint32_t& r1, uint32_t& r2, uint32_t& r3) {
    asm volatile("ldmatrix.sync.aligned.m8n8.x4.shared.b16 {%0,%1,%2,%3}, [%4];"
                 : "=r"(r0), "=r"(r1), "=r"(r2), "=r"(r3) : "r"(addr));
}
DEVINL void ldsm_x4_t(uint32_t addr, uint32_t& r0, uint32_t& r1, uint32_t& r2, uint32_t& r3) {
    asm volatile("ldmatrix.sync.aligned.m8n8.x4.trans.shared.b16 {%0,%1,%2,%3}, [%4];"
                 : "=r"(r0), "=r"(r1), "=r"(r2), "=r"(r3) : "r"(addr));
}
DEVINL void cp16(void* s, const void* g) {
    uint32_t sa = (uint32_t)__cvta_generic_to_shared(s);
    asm volatile("cp.async.cg.shared.global [%0], [%1], 16;\n" :: "r"(sa), "l"(g));
}
DEVINL void cp_commit() { asm volatile("cp.async.commit_group;\n"); }
template <int N> DEVINL void cp_wait() { asm volatile("cp.async.wait_group %0;\n" :: "n"(N)); }

// ---------------------------------------------------------------------------
// Pre-pass 1: round x (fp32 [8192][1024]) -> g_xh (f16x2 words)
// ---------------------------------------------------------------------------
__global__ void conv_x(const float* __restrict__ x)
{
    size_t idx = (size_t)blockIdx.x * 1024 + threadIdx.x;   // 4M words
    float2 v = ((const float2*)x)[idx];
    g_xh[idx] = pack_h2(v.x, v.y);
}

// ---------------------------------------------------------------------------
// Pre-pass 2: transpose + round W (fp32 [1024][N]) -> [N][512 words] hi only.
// ---------------------------------------------------------------------------
__global__ void conv_wT(const float* __restrict__ W, int N, int which)
{
    __shared__ float ts[64][33];
    uint32_t* Wh = which ? g_wph : g_wth;
    const int k0 = blockIdx.x * 64, n0 = blockIdx.y * 32;
    const int tx = threadIdx.x, ty = threadIdx.y;
#pragma unroll
    for (int i = 0; i < 8; i++)
        ts[ty + i * 8][tx] = W[(size_t)(k0 + ty + i * 8) * N + n0 + tx];
    __syncthreads();
#pragma unroll
    for (int i = 0; i < 4; i++) {
        int n = ty + i * 8;
        Wh[(size_t)(n0 + n) * 512 + (k0 >> 1) + tx] = pack_h2(ts[2 * tx][n], ts[2 * tx + 1][n]);
    }
}

// ---------------------------------------------------------------------------
// fp16 1-term GEMM (R11 config): C = A(Mx1024) W^T + bias.
// CTA 128x128, BK=32, 3-stage cp.async, 2 CTAs/SM. Warp tile 64x32.
// EPI=0: A=x -> scatter q/k/v hi (head-major). EPI=1: A=attn -> out fp32.
// ---------------------------------------------------------------------------
constexpr int P_LD = 20;                       // words/row (16 + 4 pad)
constexpr int P_ARR_W = 128 * P_LD;            // 2560 words
constexpr int P_ARR_B = P_ARR_W * 4;           // 10240 B
constexpr int P_STG_W = 2 * P_ARR_W;           // 5120 words (A | B)
constexpr int P_STG_B = P_STG_W * 4;           // 20480 B
constexpr int G_SMEM = 3 * P_STG_B;            // 61440 B

template <int EPI>
__global__ void __launch_bounds__(256, 2)
h_gemm(const float* __restrict__ bias, float* __restrict__ out)
{
    extern __shared__ uint32_t sw[];
    const uint32_t* Agh = EPI ? g_ah : g_xh;
    const uint32_t* Bgh = EPI ? g_wph : g_wth;

    const int tid = threadIdx.x, wid = tid >> 5, lid = tid & 31;
    const int wm = wid >> 2, wn = wid & 3;
    const int g = lid >> 2, tg = lid & 3;
    const int cm = blockIdx.y * 128, cn = blockIdx.x * 128;
    const uint32_t smb = (uint32_t)__cvta_generic_to_shared(sw);

    const uint32_t a_fb = smb + 4u * ((wm * 64 + (lid & 15)) * P_LD + (lid >> 4) * 4);
    const uint32_t b_fb = smb + 4u * ((wn * 32 + ((lid >> 4) & 1) * 8 + (lid & 7)) * P_LD
                                      + ((lid >> 3) & 1) * 4) + (uint32_t)P_ARR_B;

    const int row = tid >> 1;
    const int ch0 = (tid & 1) * 2;

    auto load_stage = [&](int kt, int s) {
#pragma unroll
        for (int i = 0; i < 2; i++) {
            int c = ch0 + i;
            uint32_t dst = (uint32_t)(s * P_STG_W + row * P_LD + c * 4);
            size_t asrc = (size_t)(cm + row) * 512 + kt * 16 + c * 4;
            size_t bsrc = (size_t)(cn + row) * 512 + kt * 16 + c * 4;
            cp16(sw + dst,           Agh + asrc);
            cp16(sw + dst + P_ARR_W, Bgh + bsrc);
        }
    };

    float acc[4][4][4];
#pragma unroll
    for (int i = 0; i < 4; i++)
#pragma unroll
        for (int j = 0; j < 4; j++)
#pragma unroll
            for (int e = 0; e < 4; e++) acc[i][j][e] = 0.f;

    constexpr int NT = 32;                     // K=1024 / 32
    load_stage(0, 0); cp_commit();
    load_stage(1, 1); cp_commit();

    for (int kt = 0; kt < NT; kt++) {
        cp_wait<1>();
        __syncthreads();
        if (kt + 2 < NT) load_stage(kt + 2, (kt + 2) % 3);
        cp_commit();

        const uint32_t sb = (uint32_t)((kt % 3) * P_STG_B);
#pragma unroll
        for (int ks = 0; ks < 2; ks++) {
            uint32_t ah[4][4], b[4][2];
#pragma unroll
            for (int mi = 0; mi < 4; mi++) {
                uint32_t ad = a_fb + sb + 4u * (mi * 16 * P_LD + ks * 8);
                ldsm_x4(ad, ah[mi][0], ah[mi][1], ah[mi][2], ah[mi][3]);
            }
#pragma unroll
            for (int p = 0; p < 2; p++)
                ldsm_x4(b_fb + sb + 4u * (p * 16 * P_LD + ks * 8),
                        b[2 * p][0], b[2 * p][1], b[2 * p + 1][0], b[2 * p + 1][1]);
#pragma unroll
            for (int mi = 0; mi < 4; mi++)
#pragma unroll
                for (int nj = 0; nj < 4; nj++)
                    mma_f16(acc[mi][nj], ah[mi], b[nj], acc[mi][nj]);
        }
    }

    // Epilogue
#pragma unroll
    for (int mi = 0; mi < 4; mi++) {
#pragma unroll
        for (int nj = 0; nj < 4; nj++) {
            int col0 = cn + wn * 32 + nj * 8 + 2 * tg;       // even
            float2 v0 = make_float2(acc[mi][nj][0] + bias[col0],
                                    acc[mi][nj][1] + bias[col0 + 1]);
            float2 v1 = make_float2(acc[mi][nj][2] + bias[col0],
                                    acc[mi][nj][3] + bias[col0 + 1]);
            int row0 = cm + wm * 64 + mi * 16 + g;
            int row1 = row0 + 8;
            if (EPI == 1) {
                *(float2*)&out[(size_t)row0 * 1024 + col0] = v0;
                *(float2*)&out[(size_t)row1 * 1024 + col0] = v1;
            } else {
                int t = col0 >> 10;                // 0:q 1:k 2:v
                int r1 = col0 & 1023;
                int h = r1 >> 6, d = r1 & 63;      // d even
                int b0 = row0 >> 11, s0 = row0 & 2047;
                int b1 = row1 >> 11, s1 = row1 & 2047;
                size_t w0 = ((size_t)(b0 * Hc + h) * Sc + s0) * 32 + (d >> 1);
                size_t w1 = ((size_t)(b1 * Hc + h) * Sc + s1) * 32 + (d >> 1);
                uint32_t* dst = (t == 0) ? g_qh : (t == 1) ? g_kh : g_vh;
                dst[w0] = pack_h2(v0.x, v0.y);
                dst[w1] = pack_h2(v1.x, v1.y);
            }
        }
    }
}

// ---------------------------------------------------------------------------
// Flash attention: causal, hd=64, k-blocks of 64.
// QK^T in fp16-ACC mma (2x rate), unpacked to f32 for mask/softmax.
// Softmax: ex2.approx.f16x2 -> packed P fragments. Row-sum l via ones-mma.
// PV fp32-acc. 3-stage cp.async. 2 CTAs/SM. Heavy q-blocks first.
// ---------------------------------------------------------------------------
constexpr int F_LD = 36;                       // words per 64-half row
constexpr int F_TW = 64 * F_LD;                // 2304 words per stage
constexpr int F_VB0 = 3 * F_TW;                // V area word offset
constexpr int FLASH_SMEM = 6 * F_TW * 4;       // 55296 B

__global__ void __launch_bounds__(256, 2)
flash_kernel()
{
    extern __shared__ uint32_t smw[];
    const uint32_t smb = (uint32_t)__cvta_generic_to_shared(smw);

    const int tid = threadIdx.x, wid = tid >> 5, lid = tid & 31;
    const int g = lid >> 2, tg = lid & 3;
    const int qb = (int)gridDim.x - 1 - (int)blockIdx.x;   // heavy blocks first
    const int head = blockIdx.y;

    const uint32_t* Qh = g_qh + (size_t)head * Sc * 32 + (size_t)qb * 128 * 32;
    const uint32_t* Kh = g_kh + (size_t)head * Sc * 32;
    const uint32_t* Vh = g_vh + (size_t)head * Sc * 32;

    // Stage Q hi -> V area (128 rows x 36w stride).
#pragma unroll
    for (int i = 0; i < 4; i++) {
        int idx = tid + i * 256;
        int r = idx >> 3, c = idx & 7;
        cp16(smw + F_VB0 + r * F_LD + c * 4, Qh + (size_t)r * 32 + c * 4);
    }
    cp_commit();
    cp_wait<0>();
    __syncthreads();

    uint32_t qh[4][4];
    {
        uint32_t qo = smb + 4u * F_VB0
                    + 4u * ((wid * 16 + (lid & 15)) * F_LD + (lid >> 4) * 4);
#pragma unroll
        for (int ks = 0; ks < 4; ks++)
            ldsm_x4(qo + 4u * (ks * 8), qh[ks][0], qh[ks][1], qh[ks][2], qh[ks][3]);
    }
    __syncthreads();                           // K/V areas now reusable

    auto load_tile = [&](int kb, int s) {
        size_t kbase = (size_t)kb * 64;
#pragma unroll
        for (int i = 0; i < 2; i++) {
            int idx = tid + i * 256;
            int r = idx >> 3, c = idx & 7;
            uint32_t dk = (uint32_t)(s * F_TW + r * F_LD + c * 4);
            cp16(smw + dk,         Kh + (kbase + r) * 32 + c * 4);
            cp16(smw + F_VB0 + dk, Vh + (kbase + r) * 32 + c * 4);
        }
    };

    const int nkb = 2 * qb + 2;                // 64-wide k-blocks
    load_tile(0, 0); cp_commit();
    load_tile(1, 1); cp_commit();

    float o[8][4];
#pragma unroll
    for (int j = 0; j < 8; j++)
#pragma unroll
        for (int e = 0; e < 4; e++) o[j][e] = 0.f;
    float lacc[4] = {0.f, 0.f, 0.f, 0.f};      // row-sum accumulator (ones-mma)
    float m0 = -1e30f, m1 = -1e30f;

    const float scale = 0.125f;
    const float LOG2E = 1.4426950408889634f;
    const int row0g = qb * 128 + wid * 16 + g;
    const int row1g = row0g + 8;
    const uint32_t b_ones[2] = {0x3C003C00u, 0x3C003C00u};   // f16 1.0 x2

    const uint32_t k_fb = smb + 4u * ((((lid >> 4) & 1) * 8 + (lid & 7)) * F_LD
                                      + ((lid >> 3) & 1) * 4);
    const uint32_t v_fb = smb + 4u * F_VB0
                        + 4u * ((((lid >> 3) & 1) * 8 + (lid & 7)) * F_LD)
                        + (uint32_t)(lid >> 4) * 16;

    for (int kb = 0; kb < nkb; kb++) {
        cp_wait<1>();
        __syncthreads();
        if (kb + 2 < nkb) load_tile(kb + 2, (kb + 2) % 3);
        cp_commit();

        const uint32_t stb = (uint32_t)((kb % 3) * F_TW * 4);

        // S = Q K^T (16 q-rows x 64 k-cols per warp), fp16 ACCUMULATOR (2x rate)
        uint32_t sf[8][2];
#pragma unroll
        for (int nj = 0; nj < 8; nj++) { sf[nj][0] = 0u; sf[nj][1] = 0u; }
#pragma unroll
        for (int ks = 0; ks < 4; ks++) {
            uint32_t kd = k_fb + stb + 4u * (ks * 8);
#pragma unroll
            for (int p = 0; p < 2; p++) {
                uint32_t b0[2], b1[2];
                ldsm_x4(kd + 4u * (2 * p * 16 * F_LD), b0[0], b0[1], b1[0], b1[1]);
                mma_f16acc(sf[4 * p],     qh[ks], b0, sf[4 * p]);
                mma_f16acc(sf[4 * p + 1], qh[ks], b1, sf[4 * p + 1]);
                uint32_t c0[2], c1[2];
                ldsm_x4(kd + 4u * ((2 * p + 1) * 16 * F_LD), c0[0], c0[1], c1[0], c1[1]);
                mma_f16acc(sf[4 * p + 2], qh[ks], c0, sf[4 * p + 2]);
                mma_f16acc(sf[4 * p + 3], qh[ks], c1, sf[4 * p + 3]);
            }
        }

        // unpack to f32, scale + causal mask
        float sacc[8][4];
#pragma unroll
        for (int nj = 0; nj < 8; nj++) {
            unpack_h2(sf[nj][0], sacc[nj][0], sacc[nj][1]);
            unpack_h2(sf[nj][1], sacc[nj][2], sacc[nj][3]);
#pragma unroll
            for (int e = 0; e < 4; e++) {
                int col = kb * 64 + nj * 8 + 2 * tg + (e & 1);
                int row = (e & 2) ? row1g : row0g;
                float v = sacc[nj][e] * scale;
                sacc[nj][e] = (col > row) ? -1e30f : v;
            }
        }

        // online softmax: row max
        float rmax0 = -1e30f, rmax1 = -1e30f;
#pragma unroll
        for (int nj = 0; nj < 8; nj++) {
            rmax0 = fmaxf(rmax0, fmaxf(sacc[nj][0], sacc[nj][1]));
            rmax1 = fmaxf(rmax1, fmaxf(sacc[nj][2], sacc[nj][3]));
        }
        rmax0 = fmaxf(rmax0, __shfl_xor_sync(0xffffffffu, rmax0, 1));
        rmax0 = fmaxf(rmax0, __shfl_xor_sync(0xffffffffu, rmax0, 2));
        rmax1 = fmaxf(rmax1, __shfl_xor_sync(0xffffffffu, rmax1, 1));
        rmax1 = fmaxf(rmax1, __shfl_xor_sync(0xffffffffu, rmax1, 2));

        float nm0 = fmaxf(m0, rmax0), nm1 = fmaxf(m1, rmax1);
        float alpha0 = exp2f((m0 - nm0) * LOG2E);
        float alpha1 = exp2f((m1 - nm1) * LOG2E);
        float c0 = nm0 * LOG2E, c1 = nm1 * LOG2E;

        // exponentials in fp16x2: result IS the packed P fragment word
        uint32_t pp[8], pq[8];
#pragma unroll
        for (int nj = 0; nj < 8; nj++) {
            pp[nj] = ex2_h2(fmaf(sacc[nj][0], LOG2E, -c0), fmaf(sacc[nj][1], LOG2E, -c0));
            pq[nj] = ex2_h2(fmaf(sacc[nj][2], LOG2E, -c1), fmaf(sacc[nj][3], LOG2E, -c1));
        }

        m0 = nm0; m1 = nm1;
        lacc[0] *= alpha0; lacc[1] *= alpha0;
        lacc[2] *= alpha1; lacc[3] *= alpha1;
#pragma unroll
        for (int j = 0; j < 8; j++) {
            o[j][0] *= alpha0; o[j][1] *= alpha0;
            o[j][2] *= alpha1; o[j][3] *= alpha1;
        }

        // O += P V, and lacc += P * ones (row sums via tensor core)
#pragma unroll
        for (int ks = 0; ks < 4; ks++) {
            uint32_t pa[4];
            pa[0] = pp[2 * ks];
            pa[1] = pq[2 * ks];
            pa[2] = pp[2 * ks + 1];
            pa[3] = pq[2 * ks + 1];
            mma_f16(lacc, pa, b_ones, lacc);
            uint32_t vd = v_fb + stb + 4u * (ks * 16 * F_LD);
#pragma unroll
            for (int p = 0; p < 4; p++) {
                uint32_t b0[2], b1[2];
                ldsm_x4_t(vd + (uint32_t)p * 32, b0[0], b0[1], b1[0], b1[1]);
                mma_f16(o[2 * p],     pa, b0, o[2 * p]);
                mma_f16(o[2 * p + 1], pa, b1, o[2 * p + 1]);
            }
        }
    }

    // Epilogue: write attn as fp16 hi into g_ah [8192][512 words]
    {
        int b = head >> 4, h = head & 15;
        int s0 = qb * 128 + wid * 16 + g;
        float inv0 = 1.f / lacc[0], inv1 = 1.f / lacc[2];
        size_t base0 = ((size_t)b * Sc + s0) * 512 + h * 32;
        size_t base1 = ((size_t)b * Sc + s0 + 8) * 512 + h * 32;
#pragma unroll
        for (int nj = 0; nj < 8; nj++) {
            int dw = nj * 4 + tg;
            g_ah[base0 + dw] = pack_h2(o[nj][0] * inv0, o[nj][1] * inv0);
            g_ah[base1 + dw] = pack_h2(o[nj][2] * inv1, o[nj][3] * inv1);
        }
    }
}

// ---------------------------------------------------------------------------
extern "C" void kernel_launch(void* const* d_in, const int* in_sizes, int n_in,
                              void* d_out, int out_size)
{
    (void)in_sizes; (void)n_in; (void)out_size;
    const float* x      = (const float*)d_in[0];
    const float* w_attn = (const float*)d_in[2];
    const float* b_attn = (const float*)d_in[3];
    const float* w_proj = (const float*)d_in[4];
    const float* b_proj = (const float*)d_in[5];
    float* out = (float*)d_out;

    cudaFuncSetAttribute(h_gemm<0>,    cudaFuncAttributeMaxDynamicSharedMemorySize, G_SMEM);
    cudaFuncSetAttribute(h_gemm<1>,    cudaFuncAttributeMaxDynamicSharedMemorySize, G_SMEM);
    cudaFuncSetAttribute(flash_kernel, cudaFuncAttributeMaxDynamicSharedMemorySize, FLASH_SMEM);

    // Pre-pass: round/transpose inputs to fp16
    conv_x<<<(Mc * 512) / 1024, 1024>>>(x);
    conv_wT<<<dim3(16, NQKV / 32), dim3(32, 8)>>>(w_attn, NQKV, 0);
    conv_wT<<<dim3(16, Dc / 32),   dim3(32, 8)>>>(w_proj, Dc, 1);

    // 1) QKV GEMM (1-term, BK=32) -> q/k/v hi (head-major)
    h_gemm<0><<<dim3(NQKV / 128, Mc / 128), 256, G_SMEM>>>(b_attn, nullptr);
    // 2) causal flash attention -> attn hi
    flash_kernel<<<dim3(Sc / 128, Bc * Hc), 256, FLASH_SMEM>>>();
    // 3) proj GEMM (1-term, BK=32) -> out fp32
    h_gemm<1><<<dim3(Dc / 128, Mc / 128), 256, G_SMEM>>>(b_proj, out);
}

// round 15
// speedup vs baseline: 1.1322x; 1.0208x over previous
#include <cuda_runtime.h>
#include <cstdint>

#define DEVINL __device__ __forceinline__

constexpr int Bc = 4, Sc = 2048, Dc = 1024, Hc = 16;
constexpr int Mc = Bc * Sc;           // 8192
constexpr int NQKV = 3 * Dc;          // 3072

// ---------------------------------------------------------------------------
// Scratch (__device__ globals). All fp16 data stored as packed f16x2 words.
// ---------------------------------------------------------------------------
__device__ uint32_t g_xh[(size_t)Mc * 512];                              // x hi [8192][512]
__device__ uint32_t g_wth[(size_t)NQKV * 512];                           // wA^T hi [3072][512]
__device__ uint32_t g_wph[(size_t)Dc * 512];                             // wP^T hi [1024][512]
__device__ uint32_t g_qh[(size_t)64 * Sc * 32];                          // q hi [64][2048][32]
__device__ uint32_t g_kh[(size_t)64 * Sc * 32];                          // k hi
__device__ uint32_t g_vh[(size_t)64 * Sc * 32];                          // v hi
__device__ uint32_t g_ah[(size_t)Mc * 512];                              // attn hi [8192][512]

// ---------------------------------------------------------------------------
// Helpers
// ---------------------------------------------------------------------------
DEVINL uint32_t pack_h2(float x0, float x1) {
    uint32_t h;
    asm("cvt.rn.f16x2.f32 %0, %1, %2;" : "=r"(h) : "f"(x1), "f"(x0));
    return h;
}
DEVINL void unpack_h2(uint32_t h, float& x0, float& x1) {
    asm("{\n\t.reg .f16 lo, hi;\n\tmov.b32 {lo, hi}, %2;\n\t"
        "cvt.f32.f16 %0, lo;\n\tcvt.f32.f16 %1, hi;\n\t}"
        : "=f"(x0), "=f"(x1) : "r"(h));
}
DEVINL uint32_t ex2_h2(float d0, float d1) {
    uint32_t din = pack_h2(d0, d1);
    uint32_t r;
    asm("ex2.approx.f16x2 %0, %1;" : "=r"(r) : "r"(din));
    return r;
}
DEVINL void mma_f16(float d[4], const uint32_t a[4], const uint32_t b[2], const float c[4]) {
    asm volatile(
        "mma.sync.aligned.m16n8k16.row.col.f32.f16.f16.f32 "
        "{%0,%1,%2,%3}, {%4,%5,%6,%7}, {%8,%9}, {%10,%11,%12,%13};\n"
        : "=f"(d[0]), "=f"(d[1]), "=f"(d[2]), "=f"(d[3])
        : "r"(a[0]), "r"(a[1]), "r"(a[2]), "r"(a[3]),
          "r"(b[0]), "r"(b[1]),
          "f"(c[0]), "f"(c[1]), "f"(c[2]), "f"(c[3]));
}
// fp16-accumulator mma (2x HMMA rate); D/C are f16x2 pairs.
DEVINL void mma_f16acc(uint32_t d[2], const uint32_t a[4], const uint32_t b[2], const uint32_t c[2]) {
    asm volatile(
        "mma.sync.aligned.m16n8k16.row.col.f16.f16.f16.f16 "
        "{%0,%1}, {%2,%3,%4,%5}, {%6,%7}, {%8,%9};\n"
        : "=r"(d[0]), "=r"(d[1])
        : "r"(a[0]), "r"(a[1]), "r"(a[2]), "r"(a[3]),
          "r"(b[0]), "r"(b[1]),
          "r"(c[0]), "r"(c[1]));
}
DEVINL void ldsm_x4(uint32_t addr, uint32_t& r0, uint32_t& r1, uint32_t& r2, uint32_t& r3) {
    asm volatile("ldmatrix.sync.aligned.m8n8.x4.shared.b16 {%0,%1,%2,%3}, [%4];"
                 : "=r"(r0), "=r"(r1), "=r"(r2), "=r"(r3) : "r"(addr));
}
DEVINL void ldsm_x4_t(uint32_t addr, uint32_t& r0, uint32_t& r1, uint32_t& r2, uint32_t& r3) {
    asm volatile("ldmatrix.sync.aligned.m8n8.x4.trans.shared.b16 {%0,%1,%2,%3}, [%4];"
                 : "=r"(r0), "=r"(r1), "=r"(r2), "=r"(r3) : "r"(addr));
}
DEVINL void cp16(void* s, const void* g) {
    uint32_t sa = (uint32_t)__cvta_generic_to_shared(s);
    asm volatile("cp.async.cg.shared.global [%0], [%1], 16;\n" :: "r"(sa), "l"(g));
}
DEVINL void cp_commit() { asm volatile("cp.async.commit_group;\n"); }
template <int N> DEVINL void cp_wait() { asm volatile("cp.async.wait_group %0;\n" :: "n"(N)); }

// ---------------------------------------------------------------------------
// Pre-pass 1: round x (fp32 [8192][1024]) -> g_xh (f16x2 words), float4 loads
// ---------------------------------------------------------------------------
__global__ void conv_x(const float* __restrict__ x)
{
    size_t idx = (size_t)blockIdx.x * 1024 + threadIdx.x;   // 2M float4s
    float4 v = ((const float4*)x)[idx];
    *(uint2*)&g_xh[idx * 2] = make_uint2(pack_h2(v.x, v.y), pack_h2(v.z, v.w));
}

// ---------------------------------------------------------------------------
// Pre-pass 2: transpose + round W (fp32 [1024][N]) -> [N][512 words] hi only.
// ---------------------------------------------------------------------------
__global__ void conv_wT(const float* __restrict__ W, int N, int which)
{
    __shared__ float ts[64][33];
    uint32_t* Wh = which ? g_wph : g_wth;
    const int k0 = blockIdx.x * 64, n0 = blockIdx.y * 32;
    const int tx = threadIdx.x, ty = threadIdx.y;
#pragma unroll
    for (int i = 0; i < 8; i++)
        ts[ty + i * 8][tx] = W[(size_t)(k0 + ty + i * 8) * N + n0 + tx];
    __syncthreads();
#pragma unroll
    for (int i = 0; i < 4; i++) {
        int n = ty + i * 8;
        Wh[(size_t)(n0 + n) * 512 + (k0 >> 1) + tx] = pack_h2(ts[2 * tx][n], ts[2 * tx + 1][n]);
    }
}

// ---------------------------------------------------------------------------
// fp16 1-term GEMM: C = A(Mx1024) W^T + bias.
// CTA 128x128, BK=32, 3-stage cp.async, 2 CTAs/SM. Warp tile 64x32.
// EPI=0: A=x -> scatter q/k/v hi (head-major). EPI=1: A=attn -> out fp32.
// ---------------------------------------------------------------------------
constexpr int P_LD = 20;                       // words/row (16 + 4 pad)
constexpr int P_ARR_W = 128 * P_LD;            // 2560 words
constexpr int P_ARR_B = P_ARR_W * 4;           // 10240 B
constexpr int P_STG_W = 2 * P_ARR_W;           // 5120 words (A | B)
constexpr int P_STG_B = P_STG_W * 4;           // 20480 B
constexpr int G_SMEM = 3 * P_STG_B;            // 61440 B

template <int EPI>
__global__ void __launch_bounds__(256, 2)
h_gemm(const float* __restrict__ bias, float* __restrict__ out)
{
    extern __shared__ uint32_t sw[];
    const uint32_t* Agh = EPI ? g_ah : g_xh;
    const uint32_t* Bgh = EPI ? g_wph : g_wth;

    const int tid = threadIdx.x, wid = tid >> 5, lid = tid & 31;
    const int wm = wid >> 2, wn = wid & 3;
    const int g = lid >> 2, tg = lid & 3;
    const int cm = blockIdx.y * 128, cn = blockIdx.x * 128;
    const uint32_t smb = (uint32_t)__cvta_generic_to_shared(sw);

    const uint32_t a_fb = smb + 4u * ((wm * 64 + (lid & 15)) * P_LD + (lid >> 4) * 4);
    const uint32_t b_fb = smb + 4u * ((wn * 32 + ((lid >> 4) & 1) * 8 + (lid & 7)) * P_LD
                                      + ((lid >> 3) & 1) * 4) + (uint32_t)P_ARR_B;

    const int row = tid >> 1;
    const int ch0 = (tid & 1) * 2;

    auto load_stage = [&](int kt, int s) {
#pragma unroll
        for (int i = 0; i < 2; i++) {
            int c = ch0 + i;
            uint32_t dst = (uint32_t)(s * P_STG_W + row * P_LD + c * 4);
            size_t asrc = (size_t)(cm + row) * 512 + kt * 16 + c * 4;
            size_t bsrc = (size_t)(cn + row) * 512 + kt * 16 + c * 4;
            cp16(sw + dst,           Agh + asrc);
            cp16(sw + dst + P_ARR_W, Bgh + bsrc);
        }
    };

    float acc[4][4][4];
#pragma unroll
    for (int i = 0; i < 4; i++)
#pragma unroll
        for (int j = 0; j < 4; j++)
#pragma unroll
            for (int e = 0; e < 4; e++) acc[i][j][e] = 0.f;

    constexpr int NT = 32;                     // K=1024 / 32
    load_stage(0, 0); cp_commit();
    load_stage(1, 1); cp_commit();

    for (int kt = 0; kt < NT; kt++) {
        cp_wait<1>();
        __syncthreads();
        if (kt + 2 < NT) load_stage(kt + 2, (kt + 2) % 3);
        cp_commit();

        const uint32_t sb = (uint32_t)((kt % 3) * P_STG_B);
#pragma unroll
        for (int ks = 0; ks < 2; ks++) {
            uint32_t ah[4][4], b[4][2];
#pragma unroll
            for (int mi = 0; mi < 4; mi++) {
                uint32_t ad = a_fb + sb + 4u * (mi * 16 * P_LD + ks * 8);
                ldsm_x4(ad, ah[mi][0], ah[mi][1], ah[mi][2], ah[mi][3]);
            }
#pragma unroll
            for (int p = 0; p < 2; p++)
                ldsm_x4(b_fb + sb + 4u * (p * 16 * P_LD + ks * 8),
                        b[2 * p][0], b[2 * p][1], b[2 * p + 1][0], b[2 * p + 1][1]);
#pragma unroll
            for (int mi = 0; mi < 4; mi++)
#pragma unroll
                for (int nj = 0; nj < 4; nj++)
                    mma_f16(acc[mi][nj], ah[mi], b[nj], acc[mi][nj]);
        }
    }

    // Epilogue: hoist bias loads (4 distinct column pairs per thread)
    float2 bj[4];
#pragma unroll
    for (int nj = 0; nj < 4; nj++) {
        int col0 = cn + wn * 32 + nj * 8 + 2 * tg;
        bj[nj] = make_float2(bias[col0], bias[col0 + 1]);
    }
#pragma unroll
    for (int mi = 0; mi < 4; mi++) {
#pragma unroll
        for (int nj = 0; nj < 4; nj++) {
            int col0 = cn + wn * 32 + nj * 8 + 2 * tg;       // even
            float2 v0 = make_float2(acc[mi][nj][0] + bj[nj].x,
                                    acc[mi][nj][1] + bj[nj].y);
            float2 v1 = make_float2(acc[mi][nj][2] + bj[nj].x,
                                    acc[mi][nj][3] + bj[nj].y);
            int row0 = cm + wm * 64 + mi * 16 + g;
            int row1 = row0 + 8;
            if (EPI == 1) {
                *(float2*)&out[(size_t)row0 * 1024 + col0] = v0;
                *(float2*)&out[(size_t)row1 * 1024 + col0] = v1;
            } else {
                int t = col0 >> 10;                // 0:q 1:k 2:v
                int r1 = col0 & 1023;
                int h = r1 >> 6, d = r1 & 63;      // d even
                int b0 = row0 >> 11, s0 = row0 & 2047;
                int b1 = row1 >> 11, s1 = row1 & 2047;
                size_t w0 = ((size_t)(b0 * Hc + h) * Sc + s0) * 32 + (d >> 1);
                size_t w1 = ((size_t)(b1 * Hc + h) * Sc + s1) * 32 + (d >> 1);
                uint32_t* dst = (t == 0) ? g_qh : (t == 1) ? g_kh : g_vh;
                dst[w0] = pack_h2(v0.x, v0.y);
                dst[w1] = pack_h2(v1.x, v1.y);
            }
        }
    }
}

// ---------------------------------------------------------------------------
// Flash attention: causal, hd=64, k-blocks of 64.
// QK^T fp16-acc (2x rate). Mask applied only on the 2 diagonal blocks.
// Warps 0-3 skip the fully-masked final block entirely (identical results).
// Softmax via ex2.approx.f16x2; row-sum l via ones-mma. PV fp32-acc.
// 3-stage cp.async. 2 CTAs/SM. Heavy q-blocks first.
// ---------------------------------------------------------------------------
constexpr int F_LD = 36;                       // words per 64-half row
constexpr int F_TW = 64 * F_LD;                // 2304 words per stage
constexpr int F_VB0 = 3 * F_TW;                // V area word offset
constexpr int FLASH_SMEM = 6 * F_TW * 4;       // 55296 B

__global__ void __launch_bounds__(256, 2)
flash_kernel()
{
    extern __shared__ uint32_t smw[];
    const uint32_t smb = (uint32_t)__cvta_generic_to_shared(smw);

    const int tid = threadIdx.x, wid = tid >> 5, lid = tid & 31;
    const int g = lid >> 2, tg = lid & 3;
    const int qb = (int)gridDim.x - 1 - (int)blockIdx.x;   // heavy blocks first
    const int head = blockIdx.y;

    const uint32_t* Qh = g_qh + (size_t)head * Sc * 32 + (size_t)qb * 128 * 32;
    const uint32_t* Kh = g_kh + (size_t)head * Sc * 32;
    const uint32_t* Vh = g_vh + (size_t)head * Sc * 32;

    // Stage Q hi -> V area (128 rows x 36w stride).
#pragma unroll
    for (int i = 0; i < 4; i++) {
        int idx = tid + i * 256;
        int r = idx >> 3, c = idx & 7;
        cp16(smw + F_VB0 + r * F_LD + c * 4, Qh + (size_t)r * 32 + c * 4);
    }
    cp_commit();
    cp_wait<0>();
    __syncthreads();

    uint32_t qh[4][4];
    {
        uint32_t qo = smb + 4u * F_VB0
                    + 4u * ((wid * 16 + (lid & 15)) * F_LD + (lid >> 4) * 4);
#pragma unroll
        for (int ks = 0; ks < 4; ks++)
            ldsm_x4(qo + 4u * (ks * 8), qh[ks][0], qh[ks][1], qh[ks][2], qh[ks][3]);
    }
    __syncthreads();                           // K/V areas now reusable

    auto load_tile = [&](int kb, int s) {
        size_t kbase = (size_t)kb * 64;
#pragma unroll
        for (int i = 0; i < 2; i++) {
            int idx = tid + i * 256;
            int r = idx >> 3, c = idx & 7;
            uint32_t dk = (uint32_t)(s * F_TW + r * F_LD + c * 4);
            cp16(smw + dk,         Kh + (kbase + r) * 32 + c * 4);
            cp16(smw + F_VB0 + dk, Vh + (kbase + r) * 32 + c * 4);
        }
    };

    const int nkb = 2 * qb + 2;                // 64-wide k-blocks
    load_tile(0, 0); cp_commit();
    load_tile(1, 1); cp_commit();

    float o[8][4];
#pragma unroll
    for (int j = 0; j < 8; j++)
#pragma unroll
        for (int e = 0; e < 4; e++) o[j][e] = 0.f;
    float lacc[4] = {0.f, 0.f, 0.f, 0.f};      // row-sum accumulator (ones-mma)
    float m0 = -1e30f, m1 = -1e30f;

    const float scale = 0.125f;
    const float LOG2E = 1.4426950408889634f;
    const int row0g = qb * 128 + wid * 16 + g;
    const int row1g = row0g + 8;
    const uint32_t b_ones[2] = {0x3C003C00u, 0x3C003C00u};   // f16 1.0 x2

    const uint32_t k_fb = smb + 4u * ((((lid >> 4) & 1) * 8 + (lid & 7)) * F_LD
                                      + ((lid >> 3) & 1) * 4);
    const uint32_t v_fb = smb + 4u * F_VB0
                        + 4u * ((((lid >> 3) & 1) * 8 + (lid & 7)) * F_LD)
                        + (uint32_t)(lid >> 4) * 16;

    for (int kb = 0; kb < nkb; kb++) {
        cp_wait<1>();
        __syncthreads();
        if (kb + 2 < nkb) load_tile(kb + 2, (kb + 2) % 3);
        cp_commit();

        // Warps 0-3 (rows < +64 within the q-block) are fully masked in the
        // final k-block: P == 0, alpha == 1 -> skipping is bitwise identical.
        if (wid < 4 && kb == nkb - 1) continue;

        const uint32_t stb = (uint32_t)((kb % 3) * F_TW * 4);

        // S = Q K^T (16 q-rows x 64 k-cols per warp), fp16 ACCUMULATOR (2x rate)
        uint32_t sf[8][2];
#pragma unroll
        for (int nj = 0; nj < 8; nj++) { sf[nj][0] = 0u; sf[nj][1] = 0u; }
#pragma unroll
        for (int ks = 0; ks < 4; ks++) {
            uint32_t kd = k_fb + stb + 4u * (ks * 8);
#pragma unroll
            for (int p = 0; p < 2; p++) {
                uint32_t b0[2], b1[2];
                ldsm_x4(kd + 4u * (2 * p * 16 * F_LD), b0[0], b0[1], b1[0], b1[1]);
                mma_f16acc(sf[4 * p],     qh[ks], b0, sf[4 * p]);
                mma_f16acc(sf[4 * p + 1], qh[ks], b1, sf[4 * p + 1]);
                uint32_t c0[2], c1[2];
                ldsm_x4(kd + 4u * ((2 * p + 1) * 16 * F_LD), c0[0], c0[1], c1[0], c1[1]);
                mma_f16acc(sf[4 * p + 2], qh[ks], c0, sf[4 * p + 2]);
                mma_f16acc(sf[4 * p + 3], qh[ks], c1, sf[4 * p + 3]);
            }
        }

        // unpack to f32 + scale; mask only on the 2 diagonal blocks
        float sacc[8][4];
#pragma unroll
        for (int nj = 0; nj < 8; nj++) {
            unpack_h2(sf[nj][0], sacc[nj][0], sacc[nj][1]);
            unpack_h2(sf[nj][1], sacc[nj][2], sacc[nj][3]);
#pragma unroll
            for (int e = 0; e < 4; e++) sacc[nj][e] *= scale;
        }
        if (kb >= nkb - 2) {
#pragma unroll
            for (int nj = 0; nj < 8; nj++) {
#pragma unroll
                for (int e = 0; e < 4; e++) {
                    int col = kb * 64 + nj * 8 + 2 * tg + (e & 1);
                    int row = (e & 2) ? row1g : row0g;
                    if (col > row) sacc[nj][e] = -1e30f;
                }
            }
        }

        // online softmax: row max
        float rmax0 = -1e30f, rmax1 = -1e30f;
#pragma unroll
        for (int nj = 0; nj < 8; nj++) {
            rmax0 = fmaxf(rmax0, fmaxf(sacc[nj][0], sacc[nj][1]));
            rmax1 = fmaxf(rmax1, fmaxf(sacc[nj][2], sacc[nj][3]));
        }
        rmax0 = fmaxf(rmax0, __shfl_xor_sync(0xffffffffu, rmax0, 1));
        rmax0 = fmaxf(rmax0, __shfl_xor_sync(0xffffffffu, rmax0, 2));
        rmax1 = fmaxf(rmax1, __shfl_xor_sync(0xffffffffu, rmax1, 1));
        rmax1 = fmaxf(rmax1, __shfl_xor_sync(0xffffffffu, rmax1, 2));

        float nm0 = fmaxf(m0, rmax0), nm1 = fmaxf(m1, rmax1);
        float alpha0 = exp2f((m0 - nm0) * LOG2E);
        float alpha1 = exp2f((m1 - nm1) * LOG2E);
        float c0 = nm0 * LOG2E, c1 = nm1 * LOG2E;

        // exponentials in fp16x2: result IS the packed P fragment word
        uint32_t pp[8], pq[8];
#pragma unroll
        for (int nj = 0; nj < 8; nj++) {
            pp[nj] = ex2_h2(fmaf(sacc[nj][0], LOG2E, -c0), fmaf(sacc[nj][1], LOG2E, -c0));
            pq[nj] = ex2_h2(fmaf(sacc[nj][2], LOG2E, -c1), fmaf(sacc[nj][3], LOG2E, -c1));
        }

        m0 = nm0; m1 = nm1;
        lacc[0] *= alpha0; lacc[1] *= alpha0;
        lacc[2] *= alpha1; lacc[3] *= alpha1;
#pragma unroll
        for (int j = 0; j < 8; j++) {
            o[j][0] *= alpha0; o[j][1] *= alpha0;
            o[j][2] *= alpha1; o[j][3] *= alpha1;
        }

        // O += P V, and lacc += P * ones (row sums via tensor core)
#pragma unroll
        for (int ks = 0; ks < 4; ks++) {
            uint32_t pa[4];
            pa[0] = pp[2 * ks];
            pa[1] = pq[2 * ks];
            pa[2] = pp[2 * ks + 1];
            pa[3] = pq[2 * ks + 1];
            mma_f16(lacc, pa, b_ones, lacc);
            uint32_t vd = v_fb + stb + 4u * (ks * 16 * F_LD);
#pragma unroll
            for (int p = 0; p < 4; p++) {
                uint32_t b0[2], b1[2];
                ldsm_x4_t(vd + (uint32_t)p * 32, b0[0], b0[1], b1[0], b1[1]);
                mma_f16(o[2 * p],     pa, b0, o[2 * p]);
                mma_f16(o[2 * p + 1], pa, b1, o[2 * p + 1]);
            }
        }
    }

    // Epilogue: write attn as fp16 hi into g_ah [8192][512 words]
    {
        int b = head >> 4, h = head & 15;
        int s0 = qb * 128 + wid * 16 + g;
        float inv0 = 1.f / lacc[0], inv1 = 1.f / lacc[2];
        size_t base0 = ((size_t)b * Sc + s0) * 512 + h * 32;
        size_t base1 = ((size_t)b * Sc + s0 + 8) * 512 + h * 32;
#pragma unroll
        for (int nj = 0; nj < 8; nj++) {
            int dw = nj * 4 + tg;
            g_ah[base0 + dw] = pack_h2(o[nj][0] * inv0, o[nj][1] * inv0);
            g_ah[base1 + dw] = pack_h2(o[nj][2] * inv1, o[nj][3] * inv1);
        }
    }
}

// ---------------------------------------------------------------------------
extern "C" void kernel_launch(void* const* d_in, const int* in_sizes, int n_in,
                              void* d_out, int out_size)
{
    (void)in_sizes; (void)n_in; (void)out_size;
    const float* x      = (const float*)d_in[0];
    const float* w_attn = (const float*)d_in[2];
    const float* b_attn = (const float*)d_in[3];
    const float* w_proj = (const float*)d_in[4];
    const float* b_proj = (const float*)d_in[5];
    float* out = (float*)d_out;

    cudaFuncSetAttribute(h_gemm<0>,    cudaFuncAttributeMaxDynamicSharedMemorySize, G_SMEM);
    cudaFuncSetAttribute(h_gemm<1>,    cudaFuncAttributeMaxDynamicSharedMemorySize, G_SMEM);
    cudaFuncSetAttribute(flash_kernel, cudaFuncAttributeMaxDynamicSharedMemorySize, FLASH_SMEM);

    // Pre-pass: round/transpose inputs to fp16
    conv_x<<<(Mc * 256) / 1024, 1024>>>(x);           // 2M float4s / 1024
    conv_wT<<<dim3(16, NQKV / 32), dim3(32, 8)>>>(w_attn, NQKV, 0);
    conv_wT<<<dim3(16, Dc / 32),   dim3(32, 8)>>>(w_proj, Dc, 1);

    // 1) QKV GEMM (1-term, BK=32) -> q/k/v hi (head-major)
    h_gemm<0><<<dim3(NQKV / 128, Mc / 128), 256, G_SMEM>>>(b_attn, nullptr);
    // 2) causal flash attention -> attn hi
    flash_kernel<<<dim3(Sc / 128, Bc * Hc), 256, FLASH_SMEM>>>();
    // 3) proj GEMM (1-term, BK=32) -> out fp32
    h_gemm<1><<<dim3(Dc / 128, Mc / 128), 256, G_SMEM>>>(b_proj, out);
}

// round 16
// speedup vs baseline: 1.1477x; 1.0137x over previous
#include <cuda_runtime.h>
#include <cstdint>

#define DEVINL __device__ __forceinline__

constexpr int Bc = 4, Sc = 2048, Dc = 1024, Hc = 16;
constexpr int Mc = Bc * Sc;           // 8192
constexpr int NQKV = 3 * Dc;          // 3072

// ---------------------------------------------------------------------------
// Scratch (__device__ globals). All fp16 data stored as packed f16x2 words.
// ---------------------------------------------------------------------------
__device__ uint32_t g_xh[(size_t)Mc * 512];                              // x hi [8192][512]
__device__ uint32_t g_wth[(size_t)NQKV * 512];                           // wA^T hi [3072][512]
__device__ uint32_t g_wph[(size_t)Dc * 512];                             // wP^T hi [1024][512]
__device__ uint32_t g_qh[(size_t)64 * Sc * 32];                          // q hi [64][2048][32]
__device__ uint32_t g_kh[(size_t)64 * Sc * 32];                          // k hi
__device__ uint32_t g_vh[(size_t)64 * Sc * 32];                          // v hi
__device__ uint32_t g_ah[(size_t)Mc * 512];                              // attn hi [8192][512]

// ---------------------------------------------------------------------------
// Helpers
// ---------------------------------------------------------------------------
DEVINL uint32_t pack_h2(float x0, float x1) {
    uint32_t h;
    asm("cvt.rn.f16x2.f32 %0, %1, %2;" : "=r"(h) : "f"(x1), "f"(x0));
    return h;
}
DEVINL void unpack_h2(uint32_t h, float& x0, float& x1) {
    asm("{\n\t.reg .f16 lo, hi;\n\tmov.b32 {lo, hi}, %2;\n\t"
        "cvt.f32.f16 %0, lo;\n\tcvt.f32.f16 %1, hi;\n\t}"
        : "=f"(x0), "=f"(x1) : "r"(h));
}
DEVINL uint32_t ex2_h2(float d0, float d1) {
    uint32_t din = pack_h2(d0, d1);
    uint32_t r;
    asm("ex2.approx.f16x2 %0, %1;" : "=r"(r) : "r"(din));
    return r;
}
DEVINL uint32_t hmax2(uint32_t a, uint32_t b) {
    uint32_t r;
    asm("max.f16x2 %0, %1, %2;" : "=r"(r) : "r"(a), "r"(b));
    return r;
}
DEVINL void mma_f16(float d[4], const uint32_t a[4], const uint32_t b[2], const float c[4]) {
    asm volatile(
        "mma.sync.aligned.m16n8k16.row.col.f32.f16.f16.f32 "
        "{%0,%1,%2,%3}, {%4,%5,%6,%7}, {%8,%9}, {%10,%11,%12,%13};\n"
        : "=f"(d[0]), "=f"(d[1]), "=f"(d[2]), "=f"(d[3])
        : "r"(a[0]), "r"(a[1]), "r"(a[2]), "r"(a[3]),
          "r"(b[0]), "r"(b[1]),
          "f"(c[0]), "f"(c[1]), "f"(c[2]), "f"(c[3]));
}
// fp16-accumulator mma (2x HMMA rate); D/C are f16x2 pairs.
DEVINL void mma_f16acc(uint32_t d[2], const uint32_t a[4], const uint32_t b[2], const uint32_t c[2]) {
    asm volatile(
        "mma.sync.aligned.m16n8k16.row.col.f16.f16.f16.f16 "
        "{%0,%1}, {%2,%3,%4,%5}, {%6,%7}, {%8,%9};\n"
        : "=r"(d[0]), "=r"(d[1])
        : "r"(a[0]), "r"(a[1]), "r"(a[2]), "r"(a[3]),
          "r"(b[0]), "r"(b[1]),
          "r"(c[0]), "r"(c[1]));
}
DEVINL void ldsm_x4(uint32_t addr, uint32_t& r0, uint32_t& r1, uint32_t& r2, uint32_t& r3) {
    asm volatile("ldmatrix.sync.aligned.m8n8.x4.shared.b16 {%0,%1,%2,%3}, [%4];"
                 : "=r"(r0), "=r"(r1), "=r"(r2), "=r"(r3) : "r"(addr));
}
DEVINL void ldsm_x4_t(uint32_t addr, uint32_t& r0, uint32_t& r1, uint32_t& r2, uint32_t& r3) {
    asm volatile("ldmatrix.sync.aligned.m8n8.x4.trans.shared.b16 {%0,%1,%2,%3}, [%4];"
                 : "=r"(r0), "=r"(r1), "=r"(r2), "=r"(r3) : "r"(addr));
}
DEVINL void cp16(void* s, const void* g) {
    uint32_t sa = (uint32_t)__cvta_generic_to_shared(s);
    asm volatile("cp.async.cg.shared.global [%0], [%1], 16;\n" :: "r"(sa), "l"(g));
}
DEVINL void cp_commit() { asm volatile("cp.async.commit_group;\n"); }
template <int N> DEVINL void cp_wait() { asm volatile("cp.async.wait_group %0;\n" :: "n"(N)); }

// ---------------------------------------------------------------------------
// Pre-pass 1: round x (fp32 [8192][1024]) -> g_xh (f16x2 words), float4 loads
// ---------------------------------------------------------------------------
__global__ void conv_x(const float* __restrict__ x)
{
    size_t idx = (size_t)blockIdx.x * 1024 + threadIdx.x;   // 2M float4s
    float4 v = ((const float4*)x)[idx];
    *(uint2*)&g_xh[idx * 2] = make_uint2(pack_h2(v.x, v.y), pack_h2(v.z, v.w));
}

// ---------------------------------------------------------------------------
// Pre-pass 2 (merged): transpose + round both weights.
// by < 96 -> w_attn (N=3072); by >= 96 -> w_proj (N=1024).
// ---------------------------------------------------------------------------
__global__ void conv_wT(const float* __restrict__ WA, const float* __restrict__ WP)
{
    __shared__ float ts[64][33];
    const int by = blockIdx.y;
    const bool is_p = (by >= 96);
    const float* W = is_p ? WP : WA;
    uint32_t* Wh = is_p ? g_wph : g_wth;
    const int N = is_p ? Dc : NQKV;
    const int k0 = blockIdx.x * 64, n0 = (is_p ? by - 96 : by) * 32;
    const int tx = threadIdx.x, ty = threadIdx.y;
#pragma unroll
    for (int i = 0; i < 8; i++)
        ts[ty + i * 8][tx] = W[(size_t)(k0 + ty + i * 8) * N + n0 + tx];
    __syncthreads();
#pragma unroll
    for (int i = 0; i < 4; i++) {
        int n = ty + i * 8;
        Wh[(size_t)(n0 + n) * 512 + (k0 >> 1) + tx] = pack_h2(ts[2 * tx][n], ts[2 * tx + 1][n]);
    }
}

// ---------------------------------------------------------------------------
// fp16 1-term GEMM: C = A(Mx1024) W^T + bias.
// CTA 128x128, BK=32, 3-stage cp.async, 2 CTAs/SM. Warp tile 64x32.
// EPI=0: A=x -> scatter q/k/v hi (head-major). EPI=1: A=attn -> out fp32.
// ---------------------------------------------------------------------------
constexpr int P_LD = 20;                       // words/row (16 + 4 pad)
constexpr int P_ARR_W = 128 * P_LD;            // 2560 words
constexpr int P_ARR_B = P_ARR_W * 4;           // 10240 B
constexpr int P_STG_W = 2 * P_ARR_W;           // 5120 words (A | B)
constexpr int P_STG_B = P_STG_W * 4;           // 20480 B
constexpr int G_SMEM = 3 * P_STG_B;            // 61440 B

template <int EPI>
__global__ void __launch_bounds__(256, 2)
h_gemm(const float* __restrict__ bias, float* __restrict__ out)
{
    extern __shared__ uint32_t sw[];
    const uint32_t* Agh = EPI ? g_ah : g_xh;
    const uint32_t* Bgh = EPI ? g_wph : g_wth;

    const int tid = threadIdx.x, wid = tid >> 5, lid = tid & 31;
    const int wm = wid >> 2, wn = wid & 3;
    const int g = lid >> 2, tg = lid & 3;
    const int cm = blockIdx.y * 128, cn = blockIdx.x * 128;
    const uint32_t smb = (uint32_t)__cvta_generic_to_shared(sw);

    const uint32_t a_fb = smb + 4u * ((wm * 64 + (lid & 15)) * P_LD + (lid >> 4) * 4);
    const uint32_t b_fb = smb + 4u * ((wn * 32 + ((lid >> 4) & 1) * 8 + (lid & 7)) * P_LD
                                      + ((lid >> 3) & 1) * 4) + (uint32_t)P_ARR_B;

    const int row = tid >> 1;
    const int ch0 = (tid & 1) * 2;

    auto load_stage = [&](int kt, int s) {
#pragma unroll
        for (int i = 0; i < 2; i++) {
            int c = ch0 + i;
            uint32_t dst = (uint32_t)(s * P_STG_W + row * P_LD + c * 4);
            size_t asrc = (size_t)(cm + row) * 512 + kt * 16 + c * 4;
            size_t bsrc = (size_t)(cn + row) * 512 + kt * 16 + c * 4;
            cp16(sw + dst,           Agh + asrc);
            cp16(sw + dst + P_ARR_W, Bgh + bsrc);
        }
    };

    float acc[4][4][4];
#pragma unroll
    for (int i = 0; i < 4; i++)
#pragma unroll
        for (int j = 0; j < 4; j++)
#pragma unroll
            for (int e = 0; e < 4; e++) acc[i][j][e] = 0.f;

    constexpr int NT = 32;                     // K=1024 / 32
    load_stage(0, 0); cp_commit();
    load_stage(1, 1); cp_commit();

    for (int kt = 0; kt < NT; kt++) {
        cp_wait<1>();
        __syncthreads();
        if (kt + 2 < NT) load_stage(kt + 2, (kt + 2) % 3);
        cp_commit();

        const uint32_t sb = (uint32_t)((kt % 3) * P_STG_B);
#pragma unroll
        for (int ks = 0; ks < 2; ks++) {
            uint32_t ah[4][4], b[4][2];
#pragma unroll
            for (int mi = 0; mi < 4; mi++) {
                uint32_t ad = a_fb + sb + 4u * (mi * 16 * P_LD + ks * 8);
                ldsm_x4(ad, ah[mi][0], ah[mi][1], ah[mi][2], ah[mi][3]);
            }
#pragma unroll
            for (int p = 0; p < 2; p++)
                ldsm_x4(b_fb + sb + 4u * (p * 16 * P_LD + ks * 8),
                        b[2 * p][0], b[2 * p][1], b[2 * p + 1][0], b[2 * p + 1][1]);
#pragma unroll
            for (int mi = 0; mi < 4; mi++)
#pragma unroll
                for (int nj = 0; nj < 4; nj++)
                    mma_f16(acc[mi][nj], ah[mi], b[nj], acc[mi][nj]);
        }
    }

    // Epilogue: hoist bias loads
    float2 bj[4];
#pragma unroll
    for (int nj = 0; nj < 4; nj++) {
        int col0 = cn + wn * 32 + nj * 8 + 2 * tg;
        bj[nj] = make_float2(bias[col0], bias[col0 + 1]);
    }
#pragma unroll
    for (int mi = 0; mi < 4; mi++) {
#pragma unroll
        for (int nj = 0; nj < 4; nj++) {
            int col0 = cn + wn * 32 + nj * 8 + 2 * tg;       // even
            float2 v0 = make_float2(acc[mi][nj][0] + bj[nj].x,
                                    acc[mi][nj][1] + bj[nj].y);
            float2 v1 = make_float2(acc[mi][nj][2] + bj[nj].x,
                                    acc[mi][nj][3] + bj[nj].y);
            int row0 = cm + wm * 64 + mi * 16 + g;
            int row1 = row0 + 8;
            if (EPI == 1) {
                *(float2*)&out[(size_t)row0 * 1024 + col0] = v0;
                *(float2*)&out[(size_t)row1 * 1024 + col0] = v1;
            } else {
                int t = col0 >> 10;                // 0:q 1:k 2:v
                int r1 = col0 & 1023;
                int h = r1 >> 6, d = r1 & 63;      // d even
                int b0 = row0 >> 11, s0 = row0 & 2047;
                int b1 = row1 >> 11, s1 = row1 & 2047;
                size_t w0 = ((size_t)(b0 * Hc + h) * Sc + s0) * 32 + (d >> 1);
                size_t w1 = ((size_t)(b1 * Hc + h) * Sc + s1) * 32 + (d >> 1);
                uint32_t* dst = (t == 0) ? g_qh : (t == 1) ? g_kh : g_vh;
                dst[w0] = pack_h2(v0.x, v0.y);
                dst[w1] = pack_h2(v1.x, v1.y);
            }
        }
    }
}

// ---------------------------------------------------------------------------
// Flash attention: causal, hd=64, k-blocks of 128.
// QK^T fp16-acc (sf packed). Mask folded into sf as f16 -inf (diagonal block
// only). Row max via max.f16x2. Softmax exp in f16x2 -> packed P fragments.
// Row-sum via ones-mma. PV fp32-acc. 3-stage cp.async, Q staged into V stg2.
// 2 CTAs/SM. Heavy q-blocks first.
// ---------------------------------------------------------------------------
constexpr int F_LD = 36;                       // words per k-row (32 + 4 pad)
constexpr int F_TW = 128 * F_LD;               // 4608 words per tile
constexpr int F_VB0 = 3 * F_TW;                // V area word offset
constexpr int FLASH_SMEM = 6 * F_TW * 4;       // 110592 B

__global__ void __launch_bounds__(256, 2)
flash_kernel()
{
    extern __shared__ uint32_t smw[];
    const uint32_t smb = (uint32_t)__cvta_generic_to_shared(smw);

    const int tid = threadIdx.x, wid = tid >> 5, lid = tid & 31;
    const int g = lid >> 2, tg = lid & 3;
    const int qb = (int)gridDim.x - 1 - (int)blockIdx.x;   // heavy blocks first
    const int head = blockIdx.y;

    const uint32_t* Qh = g_qh + (size_t)head * Sc * 32 + (size_t)qb * 128 * 32;
    const uint32_t* Kh = g_kh + (size_t)head * Sc * 32;
    const uint32_t* Vh = g_vh + (size_t)head * Sc * 32;

    auto load_tile = [&](int kb, int s) {
        size_t kbase = (size_t)kb * 128;
#pragma unroll
        for (int i = 0; i < 4; i++) {
            int idx = tid + i * 256;           // 1024 chunks
            int r = idx >> 3, c = idx & 7;
            uint32_t dk = (uint32_t)(s * F_TW + r * F_LD + c * 4);
            cp16(smw + dk,         Kh + (kbase + r) * 32 + c * 4);
            cp16(smw + F_VB0 + dk, Vh + (kbase + r) * 32 + c * 4);
        }
    };

    // Stage Q into V stage-2 region; overlap with tiles 0,1.
    const uint32_t qstg = (uint32_t)(F_VB0 + 2 * F_TW);
#pragma unroll
    for (int i = 0; i < 4; i++) {
        int idx = tid + i * 256;
        int r = idx >> 3, c = idx & 7;
        cp16(smw + qstg + r * F_LD + c * 4, Qh + (size_t)r * 32 + c * 4);
    }
    cp_commit();
    load_tile(0, 0); cp_commit();
    load_tile(1, 1); cp_commit();

    cp_wait<2>();                              // Q done; tiles 0,1 in flight
    __syncthreads();
    uint32_t qh[4][4];
    {
        uint32_t qo = smb + 4u * qstg
                    + 4u * ((wid * 16 + (lid & 15)) * F_LD + (lid >> 4) * 4);
#pragma unroll
        for (int ks = 0; ks < 4; ks++)
            ldsm_x4(qo + 4u * (ks * 8), qh[ks][0], qh[ks][1], qh[ks][2], qh[ks][3]);
    }

    const int nkb = qb + 1;                    // 128-wide k-blocks

    float o[8][4];
#pragma unroll
    for (int j = 0; j < 8; j++)
#pragma unroll
        for (int e = 0; e < 4; e++) o[j][e] = 0.f;
    float lacc[4] = {0.f, 0.f, 0.f, 0.f};
    float m0 = -1e30f, m1 = -1e30f;            // raw-score domain

    const float SL = 0.18033688011112042f;     // (1/8) * log2(e)
    const int row0g = qb * 128 + wid * 16 + g;
    const int row1g = row0g + 8;
    const uint32_t b_ones[2] = {0x3C003C00u, 0x3C003C00u};

    const uint32_t k_fb = smb + 4u * ((((lid >> 4) & 1) * 8 + (lid & 7)) * F_LD
                                      + ((lid >> 3) & 1) * 4);
    const uint32_t v_fb = smb + 4u * F_VB0
                        + 4u * ((((lid >> 3) & 1) * 8 + (lid & 7)) * F_LD)
                        + (uint32_t)(lid >> 4) * 16;

    for (int kb = 0; kb < nkb; kb++) {
        cp_wait<1>();
        __syncthreads();
        if (kb + 2 < nkb) load_tile(kb + 2, (kb + 2) % 3);
        cp_commit();

        const uint32_t stb = (uint32_t)((kb % 3) * F_TW * 4);

        // S = Q K^T (16 q-rows x 128 k-cols per warp), fp16 accumulators
        uint32_t sf[16][2];
#pragma unroll
        for (int nj = 0; nj < 16; nj++) { sf[nj][0] = 0u; sf[nj][1] = 0u; }
#pragma unroll
        for (int ks = 0; ks < 4; ks++) {
            uint32_t kd = k_fb + stb + 4u * (ks * 8);
#pragma unroll
            for (int p = 0; p < 8; p++) {
                uint32_t b0[2], b1[2];
                ldsm_x4(kd + 4u * (p * 16 * F_LD), b0[0], b0[1], b1[0], b1[1]);
                mma_f16acc(sf[2 * p],     qh[ks], b0, sf[2 * p]);
                mma_f16acc(sf[2 * p + 1], qh[ks], b1, sf[2 * p + 1]);
            }
        }

        // Causal mask (diagonal block only): write f16 -inf into masked halves
        if (kb == nkb - 1) {
#pragma unroll
            for (int nj = 0; nj < 16; nj++) {
                int c0 = kb * 128 + nj * 8 + 2 * tg;
#pragma unroll
                for (int w = 0; w < 2; w++) {
                    int rowg = w ? row1g : row0g;
                    uint32_t v = sf[nj][w];
                    if (c0 > rowg)     v = (v & 0xFFFF0000u) | 0x0000FC00u;
                    if (c0 + 1 > rowg) v = (v & 0x0000FFFFu) | 0xFC000000u;
                    sf[nj][w] = v;
                }
            }
        }

        // Row max via packed f16 max
        uint32_t pm0 = 0xFC00FC00u, pm1 = 0xFC00FC00u;
#pragma unroll
        for (int nj = 0; nj < 16; nj++) {
            pm0 = hmax2(pm0, sf[nj][0]);
            pm1 = hmax2(pm1, sf[nj][1]);
        }
        float ra, rb, rmax0, rmax1;
        unpack_h2(pm0, ra, rb); rmax0 = fmaxf(ra, rb);
        unpack_h2(pm1, ra, rb); rmax1 = fmaxf(ra, rb);
        rmax0 = fmaxf(rmax0, __shfl_xor_sync(0xffffffffu, rmax0, 1));
        rmax0 = fmaxf(rmax0, __shfl_xor_sync(0xffffffffu, rmax0, 2));
        rmax1 = fmaxf(rmax1, __shfl_xor_sync(0xffffffffu, rmax1, 1));
        rmax1 = fmaxf(rmax1, __shfl_xor_sync(0xffffffffu, rmax1, 2));

        float nm0 = fmaxf(m0, rmax0), nm1 = fmaxf(m1, rmax1);
        float alpha0 = exp2f((m0 - nm0) * SL);
        float alpha1 = exp2f((m1 - nm1) * SL);
        float c0 = nm0 * SL, c1 = nm1 * SL;

        // exp in fp16x2: results are the packed P fragments
        uint32_t pp[16], pq[16];
#pragma unroll
        for (int nj = 0; nj < 16; nj++) {
            float s0, s1;
            unpack_h2(sf[nj][0], s0, s1);
            pp[nj] = ex2_h2(fmaf(s0, SL, -c0), fmaf(s1, SL, -c0));
            unpack_h2(sf[nj][1], s0, s1);
            pq[nj] = ex2_h2(fmaf(s0, SL, -c1), fmaf(s1, SL, -c1));
        }

        m0 = nm0; m1 = nm1;
        lacc[0] *= alpha0; lacc[1] *= alpha0;
        lacc[2] *= alpha1; lacc[3] *= alpha1;
#pragma unroll
        for (int j = 0; j < 8; j++) {
            o[j][0] *= alpha0; o[j][1] *= alpha0;
            o[j][2] *= alpha1; o[j][3] *= alpha1;
        }

        // O += P V, lacc += P * ones
#pragma unroll
        for (int ks = 0; ks < 8; ks++) {
            uint32_t pa[4];
            pa[0] = pp[2 * ks];
            pa[1] = pq[2 * ks];
            pa[2] = pp[2 * ks + 1];
            pa[3] = pq[2 * ks + 1];
            mma_f16(lacc, pa, b_ones, lacc);
            uint32_t vd = v_fb + stb + 4u * (ks * 16 * F_LD);
#pragma unroll
            for (int p = 0; p < 4; p++) {
                uint32_t b0[2], b1[2];
                ldsm_x4_t(vd + (uint32_t)p * 32, b0[0], b0[1], b1[0], b1[1]);
                mma_f16(o[2 * p],     pa, b0, o[2 * p]);
                mma_f16(o[2 * p + 1], pa, b1, o[2 * p + 1]);
            }
        }
    }
    cp_wait<0>();                              // drain any unconsumed prologue tile

    // Epilogue: write attn as fp16 hi into g_ah [8192][512 words]
    {
        int b = head >> 4, h = head & 15;
        int s0 = qb * 128 + wid * 16 + g;
        float inv0 = 1.f / lacc[0], inv1 = 1.f / lacc[2];
        size_t base0 = ((size_t)b * Sc + s0) * 512 + h * 32;
        size_t base1 = ((size_t)b * Sc + s0 + 8) * 512 + h * 32;
#pragma unroll
        for (int nj = 0; nj < 8; nj++) {
            int dw = nj * 4 + tg;
            g_ah[base0 + dw] = pack_h2(o[nj][0] * inv0, o[nj][1] * inv0);
            g_ah[base1 + dw] = pack_h2(o[nj][2] * inv1, o[nj][3] * inv1);
        }
    }
}

// ---------------------------------------------------------------------------
extern "C" void kernel_launch(void* const* d_in, const int* in_sizes, int n_in,
                              void* d_out, int out_size)
{
    (void)in_sizes; (void)n_in; (void)out_size;
    const float* x      = (const float*)d_in[0];
    const float* w_attn = (const float*)d_in[2];
    const float* b_attn = (const float*)d_in[3];
    const float* w_proj = (const float*)d_in[4];
    const float* b_proj = (const float*)d_in[5];
    float* out = (float*)d_out;

    cudaFuncSetAttribute(h_gemm<0>,    cudaFuncAttributeMaxDynamicSharedMemorySize, G_SMEM);
    cudaFuncSetAttribute(h_gemm<1>,    cudaFuncAttributeMaxDynamicSharedMemorySize, G_SMEM);
    cudaFuncSetAttribute(flash_kernel, cudaFuncAttributeMaxDynamicSharedMemorySize, FLASH_SMEM);

    // Pre-pass: round/transpose inputs to fp16
    conv_x<<<(Mc * 256) / 1024, 1024>>>(x);
    conv_wT<<<dim3(16, 128), dim3(32, 8)>>>(w_attn, w_proj);

    // 1) QKV GEMM (1-term, BK=32) -> q/k/v hi (head-major)
    h_gemm<0><<<dim3(NQKV / 128, Mc / 128), 256, G_SMEM>>>(b_attn, nullptr);
    // 2) causal flash attention (128-wide k-blocks) -> attn hi
    flash_kernel<<<dim3(Sc / 128, Bc * Hc), 256, FLASH_SMEM>>>();
    // 3) proj GEMM (1-term, BK=32) -> out fp32
    h_gemm<1><<<dim3(Dc / 128, Mc / 128), 256, G_SMEM>>>(b_proj, out);
}

// round 17
// speedup vs baseline: 1.1582x; 1.0092x over previous
#include <cuda_runtime.h>
#include <cstdint>

#define DEVINL __device__ __forceinline__

constexpr int Bc = 4, Sc = 2048, Dc = 1024, Hc = 16;
constexpr int Mc = Bc * Sc;           // 8192
constexpr int NQKV = 3 * Dc;          // 3072

// ---------------------------------------------------------------------------
// Scratch (__device__ globals). All fp16 data stored as packed f16x2 words.
// ---------------------------------------------------------------------------
__device__ uint32_t g_xh[(size_t)Mc * 512];                              // x hi [8192][512]
__device__ uint32_t g_wth[(size_t)NQKV * 512];                           // wA^T hi [3072][512]
__device__ uint32_t g_wph[(size_t)Dc * 512];                             // wP^T hi [1024][512]
__device__ uint32_t g_qh[(size_t)64 * Sc * 32];                          // q hi [64][2048][32]
__device__ uint32_t g_kh[(size_t)64 * Sc * 32];                          // k hi
__device__ uint32_t g_vh[(size_t)64 * Sc * 32];                          // v hi
__device__ uint32_t g_ah[(size_t)Mc * 512];                              // attn hi [8192][512]

// ---------------------------------------------------------------------------
// Helpers
// ---------------------------------------------------------------------------
DEVINL uint32_t pack_h2(float x0, float x1) {
    uint32_t h;
    asm("cvt.rn.f16x2.f32 %0, %1, %2;" : "=r"(h) : "f"(x1), "f"(x0));
    return h;
}
DEVINL void unpack_h2(uint32_t h, float& x0, float& x1) {
    asm("{\n\t.reg .f16 lo, hi;\n\tmov.b32 {lo, hi}, %2;\n\t"
        "cvt.f32.f16 %0, lo;\n\tcvt.f32.f16 %1, hi;\n\t}"
        : "=f"(x0), "=f"(x1) : "r"(h));
}
DEVINL uint32_t ex2_h2(float d0, float d1) {
    uint32_t din = pack_h2(d0, d1);
    uint32_t r;
    asm("ex2.approx.f16x2 %0, %1;" : "=r"(r) : "r"(din));
    return r;
}
DEVINL uint32_t hmax2(uint32_t a, uint32_t b) {
    uint32_t r;
    asm("max.f16x2 %0, %1, %2;" : "=r"(r) : "r"(a), "r"(b));
    return r;
}
DEVINL void mma_f16(float d[4], const uint32_t a[4], const uint32_t b[2], const float c[4]) {
    asm volatile(
        "mma.sync.aligned.m16n8k16.row.col.f32.f16.f16.f32 "
        "{%0,%1,%2,%3}, {%4,%5,%6,%7}, {%8,%9}, {%10,%11,%12,%13};\n"
        : "=f"(d[0]), "=f"(d[1]), "=f"(d[2]), "=f"(d[3])
        : "r"(a[0]), "r"(a[1]), "r"(a[2]), "r"(a[3]),
          "r"(b[0]), "r"(b[1]),
          "f"(c[0]), "f"(c[1]), "f"(c[2]), "f"(c[3]));
}
// fp16-accumulator mma (2x HMMA rate); D/C are f16x2 pairs.
DEVINL void mma_f16acc(uint32_t d[2], const uint32_t a[4], const uint32_t b[2], const uint32_t c[2]) {
    asm volatile(
        "mma.sync.aligned.m16n8k16.row.col.f16.f16.f16.f16 "
        "{%0,%1}, {%2,%3,%4,%5}, {%6,%7}, {%8,%9};\n"
        : "=r"(d[0]), "=r"(d[1])
        : "r"(a[0]), "r"(a[1]), "r"(a[2]), "r"(a[3]),
          "r"(b[0]), "r"(b[1]),
          "r"(c[0]), "r"(c[1]));
}
DEVINL void ldsm_x4(uint32_t addr, uint32_t& r0, uint32_t& r1, uint32_t& r2, uint32_t& r3) {
    asm volatile("ldmatrix.sync.aligned.m8n8.x4.shared.b16 {%0,%1,%2,%3}, [%4];"
                 : "=r"(r0), "=r"(r1), "=r"(r2), "=r"(r3) : "r"(addr));
}
DEVINL void ldsm_x4_t(uint32_t addr, uint32_t& r0, uint32_t& r1, uint32_t& r2, uint32_t& r3) {
    asm volatile("ldmatrix.sync.aligned.m8n8.x4.trans.shared.b16 {%0,%1,%2,%3}, [%4];"
                 : "=r"(r0), "=r"(r1), "=r"(r2), "=r"(r3) : "r"(addr));
}
DEVINL void cp16(void* s, const void* g) {
    uint32_t sa = (uint32_t)__cvta_generic_to_shared(s);
    asm volatile("cp.async.cg.shared.global [%0], [%1], 16;\n" :: "r"(sa), "l"(g));
}
DEVINL void cp_commit() { asm volatile("cp.async.commit_group;\n"); }
template <int N> DEVINL void cp_wait() { asm volatile("cp.async.wait_group %0;\n" :: "n"(N)); }

// ---------------------------------------------------------------------------
// Pre-pass 1: round x (fp32 [8192][1024]) -> g_xh (f16x2 words), float4 loads
// ---------------------------------------------------------------------------
__global__ void conv_x(const float* __restrict__ x)
{
    size_t idx = (size_t)blockIdx.x * 1024 + threadIdx.x;   // 2M float4s
    float4 v = ((const float4*)x)[idx];
    *(uint2*)&g_xh[idx * 2] = make_uint2(pack_h2(v.x, v.y), pack_h2(v.z, v.w));
}

// ---------------------------------------------------------------------------
// Pre-pass 2 (merged): transpose + round both weights.
// ---------------------------------------------------------------------------
__global__ void conv_wT(const float* __restrict__ WA, const float* __restrict__ WP)
{
    __shared__ float ts[64][33];
    const int by = blockIdx.y;
    const bool is_p = (by >= 96);
    const float* W = is_p ? WP : WA;
    uint32_t* Wh = is_p ? g_wph : g_wth;
    const int N = is_p ? Dc : NQKV;
    const int k0 = blockIdx.x * 64, n0 = (is_p ? by - 96 : by) * 32;
    const int tx = threadIdx.x, ty = threadIdx.y;
#pragma unroll
    for (int i = 0; i < 8; i++)
        ts[ty + i * 8][tx] = W[(size_t)(k0 + ty + i * 8) * N + n0 + tx];
    __syncthreads();
#pragma unroll
    for (int i = 0; i < 4; i++) {
        int n = ty + i * 8;
        Wh[(size_t)(n0 + n) * 512 + (k0 >> 1) + tx] = pack_h2(ts[2 * tx][n], ts[2 * tx + 1][n]);
    }
}

// ---------------------------------------------------------------------------
// fp16 1-term GEMM: C = A(Mx1024) W^T + bias.
// CTA 128x128, BK=32, 4-stage cp.async, 2 CTAs/SM. Warp tile 64x32.
// ---------------------------------------------------------------------------
constexpr int P_LD = 20;                       // words/row (16 + 4 pad)
constexpr int P_ARR_W = 128 * P_LD;            // 2560 words
constexpr int P_ARR_B = P_ARR_W * 4;           // 10240 B
constexpr int P_STG_W = 2 * P_ARR_W;           // 5120 words (A | B)
constexpr int P_STG_B = P_STG_W * 4;           // 20480 B
constexpr int G_SMEM = 4 * P_STG_B;            // 81920 B

template <int EPI>
__global__ void __launch_bounds__(256, 2)
h_gemm(const float* __restrict__ bias, float* __restrict__ out)
{
    extern __shared__ uint32_t sw[];
    const uint32_t* Agh = EPI ? g_ah : g_xh;
    const uint32_t* Bgh = EPI ? g_wph : g_wth;

    const int tid = threadIdx.x, wid = tid >> 5, lid = tid & 31;
    const int wm = wid >> 2, wn = wid & 3;
    const int g = lid >> 2, tg = lid & 3;
    const int cm = blockIdx.y * 128, cn = blockIdx.x * 128;
    const uint32_t smb = (uint32_t)__cvta_generic_to_shared(sw);

    const uint32_t a_fb = smb + 4u * ((wm * 64 + (lid & 15)) * P_LD + (lid >> 4) * 4);
    const uint32_t b_fb = smb + 4u * ((wn * 32 + ((lid >> 4) & 1) * 8 + (lid & 7)) * P_LD
                                      + ((lid >> 3) & 1) * 4) + (uint32_t)P_ARR_B;

    const int row = tid >> 1;
    const int ch0 = (tid & 1) * 2;

    auto load_stage = [&](int kt, int s) {
#pragma unroll
        for (int i = 0; i < 2; i++) {
            int c = ch0 + i;
            uint32_t dst = (uint32_t)(s * P_STG_W + row * P_LD + c * 4);
            size_t asrc = (size_t)(cm + row) * 512 + kt * 16 + c * 4;
            size_t bsrc = (size_t)(cn + row) * 512 + kt * 16 + c * 4;
            cp16(sw + dst,           Agh + asrc);
            cp16(sw + dst + P_ARR_W, Bgh + bsrc);
        }
    };

    float acc[4][4][4];
#pragma unroll
    for (int i = 0; i < 4; i++)
#pragma unroll
        for (int j = 0; j < 4; j++)
#pragma unroll
            for (int e = 0; e < 4; e++) acc[i][j][e] = 0.f;

    constexpr int NT = 32;                     // K=1024 / 32
    load_stage(0, 0); cp_commit();
    load_stage(1, 1); cp_commit();
    load_stage(2, 2); cp_commit();

    for (int kt = 0; kt < NT; kt++) {
        cp_wait<2>();
        __syncthreads();
        if (kt + 3 < NT) load_stage(kt + 3, (kt + 3) & 3);
        cp_commit();

        const uint32_t sb = (uint32_t)((kt & 3) * P_STG_B);
#pragma unroll
        for (int ks = 0; ks < 2; ks++) {
            uint32_t ah[4][4], b[4][2];
#pragma unroll
            for (int mi = 0; mi < 4; mi++) {
                uint32_t ad = a_fb + sb + 4u * (mi * 16 * P_LD + ks * 8);
                ldsm_x4(ad, ah[mi][0], ah[mi][1], ah[mi][2], ah[mi][3]);
            }
#pragma unroll
            for (int p = 0; p < 2; p++)
                ldsm_x4(b_fb + sb + 4u * (p * 16 * P_LD + ks * 8),
                        b[2 * p][0], b[2 * p][1], b[2 * p + 1][0], b[2 * p + 1][1]);
#pragma unroll
            for (int mi = 0; mi < 4; mi++)
#pragma unroll
                for (int nj = 0; nj < 4; nj++)
                    mma_f16(acc[mi][nj], ah[mi], b[nj], acc[mi][nj]);
        }
    }

    // Epilogue: hoist bias loads
    float2 bj[4];
#pragma unroll
    for (int nj = 0; nj < 4; nj++) {
        int col0 = cn + wn * 32 + nj * 8 + 2 * tg;
        bj[nj] = make_float2(bias[col0], bias[col0 + 1]);
    }
#pragma unroll
    for (int mi = 0; mi < 4; mi++) {
#pragma unroll
        for (int nj = 0; nj < 4; nj++) {
            int col0 = cn + wn * 32 + nj * 8 + 2 * tg;       // even
            float2 v0 = make_float2(acc[mi][nj][0] + bj[nj].x,
                                    acc[mi][nj][1] + bj[nj].y);
            float2 v1 = make_float2(acc[mi][nj][2] + bj[nj].x,
                                    acc[mi][nj][3] + bj[nj].y);
            int row0 = cm + wm * 64 + mi * 16 + g;
            int row1 = row0 + 8;
            if (EPI == 1) {
                *(float2*)&out[(size_t)row0 * 1024 + col0] = v0;
                *(float2*)&out[(size_t)row1 * 1024 + col0] = v1;
            } else {
                int t = col0 >> 10;                // 0:q 1:k 2:v
                int r1 = col0 & 1023;
                int h = r1 >> 6, d = r1 & 63;      // d even
                int b0 = row0 >> 11, s0 = row0 & 2047;
                int b1 = row1 >> 11, s1 = row1 & 2047;
                size_t w0 = ((size_t)(b0 * Hc + h) * Sc + s0) * 32 + (d >> 1);
                size_t w1 = ((size_t)(b1 * Hc + h) * Sc + s1) * 32 + (d >> 1);
                uint32_t* dst = (t == 0) ? g_qh : (t == 1) ? g_kh : g_vh;
                dst[w0] = pack_h2(v0.x, v0.y);
                dst[w1] = pack_h2(v1.x, v1.y);
            }
        }
    }
}

// ---------------------------------------------------------------------------
// Flash attention: causal, hd=64, k-blocks of 128.
// QK^T fp16-acc; diagonal block halved for warps 0-3 (upper 64 cols fully
// masked -> bitwise-identical skip). Row max via max.f16x2. Softmax exp in
// f16x2 -> packed P fragments. Row-sum via ones-mma. PV fp32-acc.
// 3-stage cp.async, Q staged into V stg2. 2 CTAs/SM. Heavy q-blocks first.
// ---------------------------------------------------------------------------
constexpr int F_LD = 36;                       // words per k-row (32 + 4 pad)
constexpr int F_TW = 128 * F_LD;               // 4608 words per tile
constexpr int F_VB0 = 3 * F_TW;                // V area word offset
constexpr int FLASH_SMEM = 6 * F_TW * 4;       // 110592 B

// One k-block of width NP*16 columns (NP = 8 full, 4 = diagonal lower half).
#define FLASH_BLOCK(NP)                                                        \
    {                                                                          \
        uint32_t sf[2 * (NP)][2];                                              \
        _Pragma("unroll")                                                      \
        for (int nj = 0; nj < 2 * (NP); nj++) { sf[nj][0] = 0u; sf[nj][1] = 0u; } \
        _Pragma("unroll")                                                      \
        for (int ks = 0; ks < 4; ks++) {                                       \
            uint32_t kd = k_fb + stb + 4u * (ks * 8);                          \
            _Pragma("unroll")                                                  \
            for (int p = 0; p < (NP); p++) {                                   \
                uint32_t b0[2], b1[2];                                         \
                ldsm_x4(kd + 4u * (p * 16 * F_LD), b0[0], b0[1], b1[0], b1[1]);\
                mma_f16acc(sf[2 * p],     qh[ks], b0, sf[2 * p]);              \
                mma_f16acc(sf[2 * p + 1], qh[ks], b1, sf[2 * p + 1]);          \
            }                                                                  \
        }                                                                      \
        if (kb == nkb - 1) {                                                   \
            _Pragma("unroll")                                                  \
            for (int nj = 0; nj < 2 * (NP); nj++) {                            \
                int c0 = kb * 128 + nj * 8 + 2 * tg;                           \
                _Pragma("unroll")                                              \
                for (int w = 0; w < 2; w++) {                                  \
                    int rowg = w ? row1g : row0g;                              \
                    uint32_t v = sf[nj][w];                                    \
                    if (c0 > rowg)     v = (v & 0xFFFF0000u) | 0x0000FC00u;    \
                    if (c0 + 1 > rowg) v = (v & 0x0000FFFFu) | 0xFC000000u;    \
                    sf[nj][w] = v;                                             \
                }                                                              \
            }                                                                  \
        }                                                                      \
        uint32_t pm0 = 0xFC00FC00u, pm1 = 0xFC00FC00u;                         \
        _Pragma("unroll")                                                      \
        for (int nj = 0; nj < 2 * (NP); nj++) {                                \
            pm0 = hmax2(pm0, sf[nj][0]);                                       \
            pm1 = hmax2(pm1, sf[nj][1]);                                       \
        }                                                                      \
        float ra, rb, rmax0, rmax1;                                            \
        unpack_h2(pm0, ra, rb); rmax0 = fmaxf(ra, rb);                         \
        unpack_h2(pm1, ra, rb); rmax1 = fmaxf(ra, rb);                         \
        rmax0 = fmaxf(rmax0, __shfl_xor_sync(0xffffffffu, rmax0, 1));          \
        rmax0 = fmaxf(rmax0, __shfl_xor_sync(0xffffffffu, rmax0, 2));          \
        rmax1 = fmaxf(rmax1, __shfl_xor_sync(0xffffffffu, rmax1, 1));          \
        rmax1 = fmaxf(rmax1, __shfl_xor_sync(0xffffffffu, rmax1, 2));          \
        float nm0 = fmaxf(m0, rmax0), nm1 = fmaxf(m1, rmax1);                  \
        float alpha0 = exp2f((m0 - nm0) * SL);                                 \
        float alpha1 = exp2f((m1 - nm1) * SL);                                 \
        float cc0 = nm0 * SL, cc1 = nm1 * SL;                                  \
        uint32_t pp[2 * (NP)], pq[2 * (NP)];                                   \
        _Pragma("unroll")                                                      \
        for (int nj = 0; nj < 2 * (NP); nj++) {                                \
            float s0, s1;                                                      \
            unpack_h2(sf[nj][0], s0, s1);                                      \
            pp[nj] = ex2_h2(fmaf(s0, SL, -cc0), fmaf(s1, SL, -cc0));           \
            unpack_h2(sf[nj][1], s0, s1);                                      \
            pq[nj] = ex2_h2(fmaf(s0, SL, -cc1), fmaf(s1, SL, -cc1));           \
        }                                                                      \
        m0 = nm0; m1 = nm1;                                                    \
        lacc[0] *= alpha0; lacc[1] *= alpha0;                                  \
        lacc[2] *= alpha1; lacc[3] *= alpha1;                                  \
        _Pragma("unroll")                                                      \
        for (int j = 0; j < 8; j++) {                                          \
            o[j][0] *= alpha0; o[j][1] *= alpha0;                              \
            o[j][2] *= alpha1; o[j][3] *= alpha1;                              \
        }                                                                      \
        _Pragma("unroll")                                                      \
        for (int ks = 0; ks < (NP); ks++) {                                    \
            uint32_t pa[4];                                                    \
            pa[0] = pp[2 * ks];                                                \
            pa[1] = pq[2 * ks];                                                \
            pa[2] = pp[2 * ks + 1];                                            \
            pa[3] = pq[2 * ks + 1];                                            \
            mma_f16(lacc, pa, b_ones, lacc);                                   \
            uint32_t vd = v_fb + stb + 4u * (ks * 16 * F_LD);                  \
            _Pragma("unroll")                                                  \
            for (int p = 0; p < 4; p++) {                                      \
                uint32_t b0[2], b1[2];                                         \
                ldsm_x4_t(vd + (uint32_t)p * 32, b0[0], b0[1], b1[0], b1[1]);  \
                mma_f16(o[2 * p],     pa, b0, o[2 * p]);                       \
                mma_f16(o[2 * p + 1], pa, b1, o[2 * p + 1]);                   \
            }                                                                  \
        }                                                                      \
    }

__global__ void __launch_bounds__(256, 2)
flash_kernel()
{
    extern __shared__ uint32_t smw[];
    const uint32_t smb = (uint32_t)__cvta_generic_to_shared(smw);

    const int tid = threadIdx.x, wid = tid >> 5, lid = tid & 31;
    const int g = lid >> 2, tg = lid & 3;
    const int qb = (int)gridDim.x - 1 - (int)blockIdx.x;   // heavy blocks first
    const int head = blockIdx.y;

    const uint32_t* Qh = g_qh + (size_t)head * Sc * 32 + (size_t)qb * 128 * 32;
    const uint32_t* Kh = g_kh + (size_t)head * Sc * 32;
    const uint32_t* Vh = g_vh + (size_t)head * Sc * 32;

    auto load_tile = [&](int kb, int s) {
        size_t kbase = (size_t)kb * 128;
#pragma unroll
        for (int i = 0; i < 4; i++) {
            int idx = tid + i * 256;           // 1024 chunks
            int r = idx >> 3, c = idx & 7;
            uint32_t dk = (uint32_t)(s * F_TW + r * F_LD + c * 4);
            cp16(smw + dk,         Kh + (kbase + r) * 32 + c * 4);
            cp16(smw + F_VB0 + dk, Vh + (kbase + r) * 32 + c * 4);
        }
    };

    // Stage Q into V stage-2 region; overlap with tiles 0,1.
    const uint32_t qstg = (uint32_t)(F_VB0 + 2 * F_TW);
#pragma unroll
    for (int i = 0; i < 4; i++) {
        int idx = tid + i * 256;
        int r = idx >> 3, c = idx & 7;
        cp16(smw + qstg + r * F_LD + c * 4, Qh + (size_t)r * 32 + c * 4);
    }
    cp_commit();
    load_tile(0, 0); cp_commit();
    load_tile(1, 1); cp_commit();

    cp_wait<2>();                              // Q done; tiles 0,1 in flight
    __syncthreads();
    uint32_t qh[4][4];
    {
        uint32_t qo = smb + 4u * qstg
                    + 4u * ((wid * 16 + (lid & 15)) * F_LD + (lid >> 4) * 4);
#pragma unroll
        for (int ks = 0; ks < 4; ks++)
            ldsm_x4(qo + 4u * (ks * 8), qh[ks][0], qh[ks][1], qh[ks][2], qh[ks][3]);
    }

    const int nkb = qb + 1;                    // 128-wide k-blocks

    float o[8][4];
#pragma unroll
    for (int j = 0; j < 8; j++)
#pragma unroll
        for (int e = 0; e < 4; e++) o[j][e] = 0.f;
    float lacc[4] = {0.f, 0.f, 0.f, 0.f};
    float m0 = -1e30f, m1 = -1e30f;            // raw-score domain

    const float SL = 0.18033688011112042f;     // (1/8) * log2(e)
    const int row0g = qb * 128 + wid * 16 + g;
    const int row1g = row0g + 8;
    const uint32_t b_ones[2] = {0x3C003C00u, 0x3C003C00u};

    const uint32_t k_fb = smb + 4u * ((((lid >> 4) & 1) * 8 + (lid & 7)) * F_LD
                                      + ((lid >> 3) & 1) * 4);
    const uint32_t v_fb = smb + 4u * F_VB0
                        + 4u * ((((lid >> 3) & 1) * 8 + (lid & 7)) * F_LD)
                        + (uint32_t)(lid >> 4) * 16;

    for (int kb = 0; kb < nkb; kb++) {
        cp_wait<1>();
        __syncthreads();
        if (kb + 2 < nkb) load_tile(kb + 2, (kb + 2) % 3);
        cp_commit();

        const uint32_t stb = (uint32_t)((kb % 3) * F_TW * 4);

        if (kb == nkb - 1 && wid < 4) {
            // Diagonal block, lower-half warps: upper 64 cols fully masked.
            FLASH_BLOCK(4)
        } else {
            FLASH_BLOCK(8)
        }
    }
    cp_wait<0>();                              // drain any unconsumed prologue tile

    // Epilogue: write attn as fp16 hi into g_ah [8192][512 words]
    {
        int b = head >> 4, h = head & 15;
        int s0 = qb * 128 + wid * 16 + g;
        float inv0 = 1.f / lacc[0], inv1 = 1.f / lacc[2];
        size_t base0 = ((size_t)b * Sc + s0) * 512 + h * 32;
        size_t base1 = ((size_t)b * Sc + s0 + 8) * 512 + h * 32;
#pragma unroll
        for (int nj = 0; nj < 8; nj++) {
            int dw = nj * 4 + tg;
            g_ah[base0 + dw] = pack_h2(o[nj][0] * inv0, o[nj][1] * inv0);
            g_ah[base1 + dw] = pack_h2(o[nj][2] * inv1, o[nj][3] * inv1);
        }
    }
}

// ---------------------------------------------------------------------------
extern "C" void kernel_launch(void* const* d_in, const int* in_sizes, int n_in,
                              void* d_out, int out_size)
{
    (void)in_sizes; (void)n_in; (void)out_size;
    const float* x      = (const float*)d_in[0];
    const float* w_attn = (const float*)d_in[2];
    const float* b_attn = (const float*)d_in[3];
    const float* w_proj = (const float*)d_in[4];
    const float* b_proj = (const float*)d_in[5];
    float* out = (float*)d_out;

    cudaFuncSetAttribute(h_gemm<0>,    cudaFuncAttributeMaxDynamicSharedMemorySize, G_SMEM);
    cudaFuncSetAttribute(h_gemm<1>,    cudaFuncAttributeMaxDynamicSharedMemorySize, G_SMEM);
    cudaFuncSetAttribute(flash_kernel, cudaFuncAttributeMaxDynamicSharedMemorySize, FLASH_SMEM);

    // Pre-pass: round/transpose inputs to fp16
    conv_x<<<(Mc * 256) / 1024, 1024>>>(x);
    conv_wT<<<dim3(16, 128), dim3(32, 8)>>>(w_attn, w_proj);

    // 1) QKV GEMM (1-term, BK=32, 4-stage) -> q/k/v hi (head-major)
    h_gemm<0><<<dim3(NQKV / 128, Mc / 128), 256, G_SMEM>>>(b_attn, nullptr);
    // 2) causal flash attention (128-wide k-blocks) -> attn hi
    flash_kernel<<<dim3(Sc / 128, Bc * Hc), 256, FLASH_SMEM>>>();
    // 3) proj GEMM (1-term, BK=32, 4-stage) -> out fp32
    h_gemm<1><<<dim3(Dc / 128, Mc / 128), 256, G_SMEM>>>(b_proj, out);
}